// round 3
// baseline (speedup 1.0000x reference)
#include <cuda_runtime.h>
#include <cuda_bf16.h>
#include <math.h>

// Problem constants
#define T_ 128
#define B_ 32
#define L_ 2
#define H_ 1024
#define E_ 1024
#define V_ 32000
#define G4H (4 * H_)          // 4096
#define MROWS (T_ * B_)       // 4096
#define DEC_OFF ((size_t)T_ * B_ * V_)   // 131072000
#define HS_OFF  (DEC_OFF)
#define CS_OFF  (DEC_OFF + (size_t)L_ * B_ * H_)

// -------------------- scratch (static device memory; no allocations) --------
__device__ float g_emb  [(size_t)MROWS * E_];      // 16 MB
__device__ float g_xproj[(size_t)MROWS * G4H];     // 64 MB
__device__ float g_out0 [(size_t)MROWS * H_];      // 16 MB
__device__ float g_out1 [(size_t)MROWS * H_];      // 16 MB
__device__ float g_hbuf [2][B_ * H_];              // double-buffered h state
__device__ unsigned g_bar;                          // grid barrier counter

// ============================= embedding gather ==============================
__global__ void embed_kernel(const int* __restrict__ inp,
                             const float* __restrict__ embw)
{
    int row = blockIdx.x;                 // t*B + b
    int tok = inp[row];
    const float4* src = (const float4*)(embw + (size_t)tok * E_);
    float4* dst = (float4*)(g_emb + (size_t)row * E_);
    dst[threadIdx.x] = src[threadIdx.x];  // 256 threads * 4 = 1024 floats
}

// ============================= fp32 NT GEMM =================================
// C[m][n] = sum_k A[m*K+k]*B[n*K+k] + b1[n] (+ b2[n])
#define BM 128
#define BN 128
#define BK 16

__global__ __launch_bounds__(256) void gemm_nt(
    const float* __restrict__ A, const float* __restrict__ B,
    const float* __restrict__ b1, const float* __restrict__ b2,
    float* __restrict__ C, int M, int N, int K)
{
    __shared__ float As[BK][BM + 4];
    __shared__ float Bs[BK][BN + 4];

    int tid = threadIdx.x;
    int bm = blockIdx.y * BM;
    int bn = blockIdx.x * BN;
    int tx = tid & 15;
    int ty = tid >> 4;

    float acc[8][8];
#pragma unroll
    for (int i = 0; i < 8; i++)
#pragma unroll
        for (int j = 0; j < 8; j++) acc[i][j] = 0.f;

    for (int k0 = 0; k0 < K; k0 += BK) {
#pragma unroll
        for (int it = 0; it < 2; it++) {
            int fid = tid + it * 256;     // 0..511 float4 slots
            int row = fid >> 2;
            int c4  = fid & 3;
            float4 av = *(const float4*)&A[(size_t)(bm + row) * K + k0 + c4 * 4];
            As[c4 * 4 + 0][row] = av.x;
            As[c4 * 4 + 1][row] = av.y;
            As[c4 * 4 + 2][row] = av.z;
            As[c4 * 4 + 3][row] = av.w;
            float4 bv = *(const float4*)&B[(size_t)(bn + row) * K + k0 + c4 * 4];
            Bs[c4 * 4 + 0][row] = bv.x;
            Bs[c4 * 4 + 1][row] = bv.y;
            Bs[c4 * 4 + 2][row] = bv.z;
            Bs[c4 * 4 + 3][row] = bv.w;
        }
        __syncthreads();

#pragma unroll
        for (int kk = 0; kk < BK; kk++) {
            float4 a0 = *(const float4*)&As[kk][ty * 4];
            float4 a1 = *(const float4*)&As[kk][ty * 4 + 64];
            float4 c0 = *(const float4*)&Bs[kk][tx * 4];
            float4 c1 = *(const float4*)&Bs[kk][tx * 4 + 64];
            float ar[8] = {a0.x, a0.y, a0.z, a0.w, a1.x, a1.y, a1.z, a1.w};
            float br[8] = {c0.x, c0.y, c0.z, c0.w, c1.x, c1.y, c1.z, c1.w};
#pragma unroll
            for (int i = 0; i < 8; i++)
#pragma unroll
                for (int j = 0; j < 8; j++)
                    acc[i][j] += ar[i] * br[j];
        }
        __syncthreads();
    }

    // epilogue: bias + store
#pragma unroll
    for (int rg = 0; rg < 2; rg++) {
#pragma unroll
        for (int i = 0; i < 4; i++) {
            int r = ty * 4 + rg * 64 + i;
            size_t crow = (size_t)(bm + r) * N + bn;
#pragma unroll
            for (int cg = 0; cg < 2; cg++) {
                int cb = tx * 4 + cg * 64;
                float4 v;
                float bx = b1[bn + cb + 0] + (b2 ? b2[bn + cb + 0] : 0.f);
                float by = b1[bn + cb + 1] + (b2 ? b2[bn + cb + 1] : 0.f);
                float bz = b1[bn + cb + 2] + (b2 ? b2[bn + cb + 2] : 0.f);
                float bw = b1[bn + cb + 3] + (b2 ? b2[bn + cb + 3] : 0.f);
                v.x = acc[rg * 4 + i][cg * 4 + 0] + bx;
                v.y = acc[rg * 4 + i][cg * 4 + 1] + by;
                v.z = acc[rg * 4 + i][cg * 4 + 2] + bz;
                v.w = acc[rg * 4 + i][cg * 4 + 3] + bw;
                *(float4*)&C[crow + cb] = v;
            }
        }
    }
}

// ========================= LSTM recurrence (persistent) ======================
// 128 CTAs, each owns 8 hidden units j. W_hh slice resident in smem as
// Wsm[jl][k][gate] with per-jl pad of 4 floats -> conflict-free float4 LDS.
// 131KB smem + __launch_bounds__(256,1) => 1 CTA/SM, 128 CTAs on 148 SMs:
// whole grid is co-resident in wave 1, so the sw grid barrier is safe.
#define REC_CTAS 128
#define JPC 8
#define WROW 4100                 // 1024*4 + 4 pad (floats per jl)
#define RNN_SMEM (JPC * WROW * 4) // 131200 bytes

__global__ void rnn_init(const float* __restrict__ h0l)
{
    int i = blockIdx.x * blockDim.x + threadIdx.x;
    for (int k = i; k < B_ * H_; k += gridDim.x * blockDim.x)
        g_hbuf[0][k] = h0l[k];
    if (i == 0) g_bar = 0u;
}

__global__ __launch_bounds__(256, 1) void rnn_kernel(
    const float* __restrict__ Whh,   // [4H, H] this layer
    const float* __restrict__ xproj, // [T*B, 4H]
    const float* __restrict__ c0l,   // [B, H]
    float* __restrict__ layer_out,   // [T*B, H]
    float* __restrict__ hs_out,      // [B, H]
    float* __restrict__ cs_out)      // [B, H]
{
    extern __shared__ float Wsm[];
    int tid = threadIdx.x;
    int cta = blockIdx.x;
    int b  = tid >> 3;           // 0..31
    int jl = tid & 7;            // 0..7
    int j  = cta * JPC + jl;

    // load W_hh slice: 32 rows (4 gates x 8 jl) of 1024
    for (int r = 0; r < 32; r++) {
        int g = r >> 3, jl2 = r & 7;
        const float* src = Whh + (size_t)(g * H_ + cta * JPC + jl2) * H_;
        for (int k = tid; k < H_; k += 256)
            Wsm[jl2 * WROW + k * 4 + g] = src[k];
    }

    float c = c0l[b * H_ + j];
    __syncthreads();

    const float4* wrow = (const float4*)(Wsm + jl * WROW);

    for (int t = 0; t < T_; t++) {
        const float4* hrow = (const float4*)(g_hbuf[t & 1] + b * H_);
        float4 acc = make_float4(0.f, 0.f, 0.f, 0.f);

#pragma unroll 4
        for (int k4 = 0; k4 < H_ / 4; k4++) {
            float4 hv = __ldcg(&hrow[k4]);     // L2 read: cross-SM coherent
            float4 w0 = wrow[k4 * 4 + 0];
            float4 w1 = wrow[k4 * 4 + 1];
            float4 w2 = wrow[k4 * 4 + 2];
            float4 w3 = wrow[k4 * 4 + 3];
            acc.x += hv.x * w0.x; acc.y += hv.x * w0.y; acc.z += hv.x * w0.z; acc.w += hv.x * w0.w;
            acc.x += hv.y * w1.x; acc.y += hv.y * w1.y; acc.z += hv.y * w1.z; acc.w += hv.y * w1.w;
            acc.x += hv.z * w2.x; acc.y += hv.z * w2.y; acc.z += hv.z * w2.z; acc.w += hv.z * w2.w;
            acc.x += hv.w * w3.x; acc.y += hv.w * w3.y; acc.z += hv.w * w3.z; acc.w += hv.w * w3.w;
        }

        int m = t * B_ + b;
        const float* xp = xproj + (size_t)m * G4H;
        float gi = acc.x + xp[j];
        float gf = acc.y + xp[H_ + j];
        float gg = acc.z + xp[2 * H_ + j];
        float go = acc.w + xp[3 * H_ + j];
        float ig = 1.f / (1.f + expf(-gi));
        float fg = 1.f / (1.f + expf(-gf));
        float gt = tanhf(gg);
        float og = 1.f / (1.f + expf(-go));
        c = fg * c + ig * gt;
        float h = og * tanhf(c);

        g_hbuf[(t + 1) & 1][b * H_ + j] = h;
        layer_out[(size_t)m * H_ + j] = h;
        if (t == T_ - 1) {
            hs_out[b * H_ + j] = h;
            cs_out[b * H_ + j] = c;
        }

        if (t < T_ - 1) {
            __threadfence();                  // publish h writes (and order)
            __syncthreads();
            if (tid == 0) {
                atomicAdd(&g_bar, 1u);
                unsigned target = (unsigned)(t + 1) * (unsigned)gridDim.x;
                while (atomicAdd(&g_bar, 0u) < target) __nanosleep(64);
                __threadfence();              // gpu-scope: invalidates L1
            }
            __syncthreads();
        }
    }
}

// ================================ launch =====================================
extern "C" void kernel_launch(void* const* d_in, const int* in_sizes, int n_in,
                              void* d_out, int out_size)
{
    (void)in_sizes; (void)n_in; (void)out_size;
    const int*   input = (const int*)  d_in[0];
    const float* h0    = (const float*)d_in[1];
    const float* c0    = (const float*)d_in[2];
    const float* embw  = (const float*)d_in[3];
    const float* Wih   = (const float*)d_in[4];
    const float* Whh   = (const float*)d_in[5];
    const float* bih   = (const float*)d_in[6];
    const float* bhh   = (const float*)d_in[7];
    const float* decW  = (const float*)d_in[8];
    const float* decb  = (const float*)d_in[9];
    float* out = (float*)d_out;

    cudaFuncSetAttribute(rnn_kernel, cudaFuncAttributeMaxDynamicSharedMemorySize, RNN_SMEM);

    float *p_emb, *p_xproj, *p_out0, *p_out1;
    cudaGetSymbolAddress((void**)&p_emb,   g_emb);
    cudaGetSymbolAddress((void**)&p_xproj, g_xproj);
    cudaGetSymbolAddress((void**)&p_out0,  g_out0);
    cudaGetSymbolAddress((void**)&p_out1,  g_out1);

    // 1. embedding
    embed_kernel<<<MROWS, 256>>>(input, embw);

    // 2. layer 0 input projection: [4096,1024] x [4096,1024]^T + b_ih0 + b_hh0
    {
        dim3 grid(G4H / BN, MROWS / BM);
        gemm_nt<<<grid, 256>>>(p_emb, Wih + 0, bih + 0, bhh + 0,
                               p_xproj, MROWS, G4H, E_);
    }

    // 3. layer 0 recurrence
    rnn_init<<<32, 256>>>(h0 + 0);
    rnn_kernel<<<REC_CTAS, 256, RNN_SMEM>>>(Whh + 0, p_xproj, c0 + 0,
                                            p_out0,
                                            out + HS_OFF + 0,
                                            out + CS_OFF + 0);

    // 4. layer 1 input projection
    {
        dim3 grid(G4H / BN, MROWS / BM);
        gemm_nt<<<grid, 256>>>(p_out0, Wih + (size_t)G4H * E_,
                               bih + G4H, bhh + G4H,
                               p_xproj, MROWS, G4H, H_);
    }

    // 5. layer 1 recurrence
    rnn_init<<<32, 256>>>(h0 + B_ * H_);
    rnn_kernel<<<REC_CTAS, 256, RNN_SMEM>>>(Whh + (size_t)G4H * H_, p_xproj,
                                            c0 + B_ * H_,
                                            p_out1,
                                            out + HS_OFF + B_ * H_,
                                            out + CS_OFF + B_ * H_);

    // 6. decoder: [4096,1024] x [32000,1024]^T + dec_b -> d_out[0:T*B*V]
    {
        dim3 grid(V_ / BN, MROWS / BM);
        gemm_nt<<<grid, 256>>>(p_out1, decW, decb, nullptr,
                               out, MROWS, V_, H_);
    }
}

// round 12
// speedup vs baseline: 1.3325x; 1.3325x over previous
#include <cuda_runtime.h>
#include <cuda_bf16.h>
#include <math.h>
#include <stdint.h>

// Problem constants
#define T_ 128
#define B_ 32
#define L_ 2
#define H_ 1024
#define E_ 1024
#define V_ 32000
#define G4H 4096
#define MROWS 4096
#define DEC_OFF ((size_t)T_ * B_ * V_)
#define HS_OFF  (DEC_OFF)
#define CS_OFF  (DEC_OFF + (size_t)L_ * B_ * H_)

// -------------------- scratch (static device memory) ------------------------
__device__ __nv_bfloat16 g_dec_hi[(size_t)V_ * H_];
__device__ __nv_bfloat16 g_dec_lo[(size_t)V_ * H_];
__device__ __nv_bfloat16 g_wih_hi[(size_t)L_ * G4H * H_];
__device__ __nv_bfloat16 g_wih_lo[(size_t)L_ * G4H * H_];
__device__ __nv_bfloat16 g_a_hi[(size_t)MROWS * H_];
__device__ __nv_bfloat16 g_a_lo[(size_t)MROWS * H_];
__device__ float g_xproj[(size_t)MROWS * G4H];
__device__ float g_out0 [(size_t)MROWS * H_];
__device__ float g_out1 [(size_t)MROWS * H_];
__device__ float g_hbuf [2][B_ * H_];
__device__ unsigned g_bar;

// ============================ helpers ========================================
__device__ __forceinline__ uint32_t smem_u32(const void* p){
    uint32_t a;
    asm("{ .reg .u64 t; cvta.to.shared.u64 t, %1; cvt.u32.u64 %0, t; }"
        : "=r"(a) : "l"(p));
    return a;
}
__device__ __forceinline__ void split1(float x, unsigned short &h, unsigned short &l){
    __nv_bfloat16 bh = __float2bfloat16(x);
    __nv_bfloat16 bl = __float2bfloat16(x - __bfloat162float(bh));
    h = *(unsigned short*)&bh;
    l = *(unsigned short*)&bl;
}

// ======================= fp32 -> bf16 hi/lo conversion =======================
__global__ void split_kernel(const float4* __restrict__ src,
                             ushort4* __restrict__ hi, ushort4* __restrict__ lo,
                             int n4){
    for (int i = blockIdx.x * blockDim.x + threadIdx.x; i < n4;
         i += gridDim.x * blockDim.x){
        float4 v = src[i];
        ushort4 h, l;
        split1(v.x, h.x, l.x); split1(v.y, h.y, l.y);
        split1(v.z, h.z, l.z); split1(v.w, h.w, l.w);
        hi[i] = h; lo[i] = l;
    }
}

// ====================== embedding gather -> bf16 hi/lo =======================
__global__ void embed_kernel(const int* __restrict__ inp,
                             const float* __restrict__ embw){
    int row = blockIdx.x;
    int tok = inp[row];
    const float4* src = (const float4*)(embw + (size_t)tok * E_);
    ushort4* dh = (ushort4*)(g_a_hi + (size_t)row * E_);
    ushort4* dl = (ushort4*)(g_a_lo + (size_t)row * E_);
    float4 v = src[threadIdx.x];
    ushort4 h, l;
    split1(v.x, h.x, l.x); split1(v.y, h.y, l.y);
    split1(v.z, h.z, l.z); split1(v.w, h.w, l.w);
    dh[threadIdx.x] = h; dl[threadIdx.x] = l;
}

// ============ bf16-split NT GEMM via mma.sync (legacy HMMA path) =============
// C[m,n] = sum_k A[m,k]*B[n,k] + b1[n] (+ b2[n])
// 128x128 CTA tile, K-stage = 64 bf16 (128B rows, SW128 swizzle), 8 warps 2x4,
// warp tile 64x32, m16n8k16 bf16 mma, 3 passes (hh, hl, lh), fp32 accum.
#define KS 64
#define TILE_B (128 * 128)          // one operand tile: 128 rows x 128B
#define STAGE_B (4 * TILE_B)        // Ahi, Alo, Bhi, Blo
#define GEMM_SMEM (2 * STAGE_B)     // 131072 B

__device__ __forceinline__ uint32_t sw_addr(uint32_t base, int row, int chunk){
    return base + row * 128 + (((chunk ^ (row & 7)) & 7) << 4);
}
__device__ __forceinline__ void ldm_x4(uint32_t addr, uint32_t r[4]){
    asm volatile("ldmatrix.sync.aligned.m8n8.x4.shared.b16 {%0,%1,%2,%3}, [%4];"
                 : "=r"(r[0]), "=r"(r[1]), "=r"(r[2]), "=r"(r[3]) : "r"(addr));
}
__device__ __forceinline__ void mma16816(float c[4], const uint32_t a[4],
                                         const uint32_t b0, const uint32_t b1){
    asm volatile(
        "mma.sync.aligned.m16n8k16.row.col.f32.bf16.bf16.f32 "
        "{%0,%1,%2,%3}, {%4,%5,%6,%7}, {%8,%9}, {%0,%1,%2,%3};"
        : "+f"(c[0]), "+f"(c[1]), "+f"(c[2]), "+f"(c[3])
        : "r"(a[0]), "r"(a[1]), "r"(a[2]), "r"(a[3]), "r"(b0), "r"(b1));
}

__global__ __launch_bounds__(256, 1)
void mma_gemm(const __nv_bfloat16* __restrict__ Ahi,
              const __nv_bfloat16* __restrict__ Alo,
              const __nv_bfloat16* __restrict__ Bhi,
              const __nv_bfloat16* __restrict__ Blo,
              const float* __restrict__ b1, const float* __restrict__ b2,
              float* __restrict__ C, int N, int K)
{
    extern __shared__ char smem[];
    uint32_t sb = smem_u32(smem);
    int tid = threadIdx.x, wid = tid >> 5, lane = tid & 31;
    int bm = blockIdx.x * 128, bn = blockIdx.y * 128;
    int wm = wid & 1, wn = wid >> 1;       // 2 x 4 warp grid

    float acc[4][4][4];
#pragma unroll
    for (int i = 0; i < 4; i++)
#pragma unroll
        for (int j = 0; j < 4; j++)
#pragma unroll
            for (int k = 0; k < 4; k++) acc[i][j][k] = 0.f;

    const int nst = K / KS;

    // ---- loader lambda-ish macro: stage s into buffer s&1 ----
#define LOAD_STAGE(s)                                                          \
    {                                                                          \
        uint32_t tb_ = sb + ((s) & 1) * STAGE_B;                               \
        for (int i = tid; i < 4096; i += 256){                                 \
            int tile = i >> 10, r = (i >> 3) & 127, seg = i & 7;               \
            const __nv_bfloat16* src = (tile == 0) ? Ahi : (tile == 1) ? Alo   \
                                     : (tile == 2) ? Bhi : Blo;                \
            int grow = ((tile < 2) ? bm : bn) + r;                             \
            const char* g = (const char*)(src + (size_t)grow * K + (s) * KS)   \
                            + seg * 16;                                        \
            uint32_t d = sw_addr(tb_ + tile * TILE_B, r, seg);                 \
            asm volatile("cp.async.cg.shared.global [%0], [%1], 16;"           \
                         :: "r"(d), "l"(g) : "memory");                        \
        }                                                                      \
        asm volatile("cp.async.commit_group;" ::: "memory");                   \
    }

    LOAD_STAGE(0);

    for (int s = 0; s < nst; s++){
        if (s + 1 < nst) LOAD_STAGE(s + 1);
        if (s + 1 < nst)
            asm volatile("cp.async.wait_group 1;" ::: "memory");
        else
            asm volatile("cp.async.wait_group 0;" ::: "memory");
        __syncthreads();

        uint32_t tb = sb + (s & 1) * STAGE_B;
        uint32_t a_hi_b = tb, a_lo_b = tb + TILE_B;
        uint32_t b_hi_b = tb + 2 * TILE_B, b_lo_b = tb + 3 * TILE_B;

#pragma unroll
        for (int k16 = 0; k16 < KS / 16; k16++){
            uint32_t ah[4][4], al[4][4], bh[4][2], bl[4][2];
            // A fragments: row = wm*64 + mt*16 + (lane&15), chunk = k16*2 + (lane>>4)
            int ar = wm * 64 + (lane & 15);
            int ac = k16 * 2 + (lane >> 4);
#pragma unroll
            for (int mt = 0; mt < 4; mt++){
                ldm_x4(sw_addr(a_hi_b, ar + mt * 16, ac), ah[mt]);
                ldm_x4(sw_addr(a_lo_b, ar + mt * 16, ac), al[mt]);
            }
            // B fragments: 2 n8-tiles per x4
            int br = wn * 32 + (lane & 7) + ((lane >> 4) & 1) * 8;
            int bc = k16 * 2 + ((lane >> 3) & 1);
#pragma unroll
            for (int np = 0; np < 2; np++){
                uint32_t r4[4];
                ldm_x4(sw_addr(b_hi_b, br + np * 16, bc), r4);
                bh[np * 2][0] = r4[0]; bh[np * 2][1] = r4[1];
                bh[np * 2 + 1][0] = r4[2]; bh[np * 2 + 1][1] = r4[3];
                ldm_x4(sw_addr(b_lo_b, br + np * 16, bc), r4);
                bl[np * 2][0] = r4[0]; bl[np * 2][1] = r4[1];
                bl[np * 2 + 1][0] = r4[2]; bl[np * 2 + 1][1] = r4[3];
            }
#pragma unroll
            for (int mt = 0; mt < 4; mt++)
#pragma unroll
                for (int nt = 0; nt < 4; nt++){
                    mma16816(acc[mt][nt], ah[mt], bh[nt][0], bh[nt][1]); // hi*hi
                    mma16816(acc[mt][nt], ah[mt], bl[nt][0], bl[nt][1]); // hi*lo
                    mma16816(acc[mt][nt], al[mt], bh[nt][0], bh[nt][1]); // lo*hi
                }
        }
        __syncthreads();
    }

    // ---- epilogue: bias + store ----
    int m0 = bm + wm * 64 + (lane >> 2);
    int n0 = bn + wn * 32 + (lane & 3) * 2;
#pragma unroll
    for (int nt = 0; nt < 4; nt++){
        int c = n0 + nt * 8;
        float bx = b1[c]     + (b2 ? b2[c]     : 0.f);
        float by = b1[c + 1] + (b2 ? b2[c + 1] : 0.f);
#pragma unroll
        for (int mt = 0; mt < 4; mt++){
            int r = m0 + mt * 16;
            float2 v0 = make_float2(acc[mt][nt][0] + bx, acc[mt][nt][1] + by);
            float2 v1 = make_float2(acc[mt][nt][2] + bx, acc[mt][nt][3] + by);
            *(float2*)&C[(size_t)r * N + c] = v0;
            *(float2*)&C[(size_t)(r + 8) * N + c] = v1;
        }
    }
#undef LOAD_STAGE
}

// ========================= LSTM recurrence (persistent) ======================
#define REC_CTAS 128
#define JPC 8
#define WROW 4100
#define RNN_SMEM (JPC * WROW * 4)

__global__ void rnn_init(const float* __restrict__ h0l)
{
    int i = blockIdx.x * blockDim.x + threadIdx.x;
    for (int k = i; k < B_ * H_; k += gridDim.x * blockDim.x)
        g_hbuf[0][k] = h0l[k];
    if (i == 0) g_bar = 0u;
}

__global__ __launch_bounds__(256, 1) void rnn_kernel(
    const float* __restrict__ Whh, const float* __restrict__ xproj,
    const float* __restrict__ c0l, float* __restrict__ layer_out,
    float* __restrict__ hs_out, float* __restrict__ cs_out)
{
    extern __shared__ float Wsm[];
    int tid = threadIdx.x;
    int cta = blockIdx.x;
    int b  = tid >> 3;
    int jl = tid & 7;
    int j  = cta * JPC + jl;

    for (int r = 0; r < 32; r++){
        int g = r >> 3, jl2 = r & 7;
        const float* src = Whh + (size_t)(g * H_ + cta * JPC + jl2) * H_;
        for (int k = tid; k < H_; k += 256)
            Wsm[jl2 * WROW + k * 4 + g] = src[k];
    }
    float c = c0l[b * H_ + j];
    __syncthreads();

    const float4* wrow = (const float4*)(Wsm + jl * WROW);

    for (int t = 0; t < T_; t++){
        const float4* hrow = (const float4*)(g_hbuf[t & 1] + b * H_);
        float4 acc = make_float4(0.f, 0.f, 0.f, 0.f);
#pragma unroll 4
        for (int k4 = 0; k4 < H_ / 4; k4++){
            float4 hv = __ldcg(&hrow[k4]);
            float4 w0 = wrow[k4 * 4 + 0];
            float4 w1 = wrow[k4 * 4 + 1];
            float4 w2 = wrow[k4 * 4 + 2];
            float4 w3 = wrow[k4 * 4 + 3];
            acc.x += hv.x * w0.x; acc.y += hv.x * w0.y; acc.z += hv.x * w0.z; acc.w += hv.x * w0.w;
            acc.x += hv.y * w1.x; acc.y += hv.y * w1.y; acc.z += hv.y * w1.z; acc.w += hv.y * w1.w;
            acc.x += hv.z * w2.x; acc.y += hv.z * w2.y; acc.z += hv.z * w2.z; acc.w += hv.z * w2.w;
            acc.x += hv.w * w3.x; acc.y += hv.w * w3.y; acc.z += hv.w * w3.z; acc.w += hv.w * w3.w;
        }
        int m = t * B_ + b;
        const float* xp = xproj + (size_t)m * G4H;
        float gi = acc.x + xp[j];
        float gf = acc.y + xp[H_ + j];
        float gg = acc.z + xp[2 * H_ + j];
        float go = acc.w + xp[3 * H_ + j];
        float ig = 1.f / (1.f + expf(-gi));
        float fg = 1.f / (1.f + expf(-gf));
        float gt = tanhf(gg);
        float og = 1.f / (1.f + expf(-go));
        c = fg * c + ig * gt;
        float h = og * tanhf(c);

        g_hbuf[(t + 1) & 1][b * H_ + j] = h;
        layer_out[(size_t)m * H_ + j] = h;
        if (t == T_ - 1){ hs_out[b * H_ + j] = h; cs_out[b * H_ + j] = c; }

        if (t < T_ - 1){
            __threadfence();
            __syncthreads();
            if (tid == 0){
                atomicAdd(&g_bar, 1u);
                unsigned target = (unsigned)(t + 1) * (unsigned)gridDim.x;
                while (atomicAdd(&g_bar, 0u) < target) __nanosleep(64);
                __threadfence();
            }
            __syncthreads();
        }
    }
}

// ================================ launch =====================================
extern "C" void kernel_launch(void* const* d_in, const int* in_sizes, int n_in,
                              void* d_out, int out_size)
{
    (void)in_sizes; (void)n_in; (void)out_size;
    const int*   input = (const int*)  d_in[0];
    const float* h0    = (const float*)d_in[1];
    const float* c0    = (const float*)d_in[2];
    const float* embw  = (const float*)d_in[3];
    const float* Wih   = (const float*)d_in[4];
    const float* Whh   = (const float*)d_in[5];
    const float* bih   = (const float*)d_in[6];
    const float* bhh   = (const float*)d_in[7];
    const float* decW  = (const float*)d_in[8];
    const float* decb  = (const float*)d_in[9];
    float* out = (float*)d_out;

    cudaFuncSetAttribute(rnn_kernel, cudaFuncAttributeMaxDynamicSharedMemorySize, RNN_SMEM);
    cudaFuncSetAttribute(mma_gemm,  cudaFuncAttributeMaxDynamicSharedMemorySize, GEMM_SMEM);

    __nv_bfloat16 *p_dec_hi, *p_dec_lo, *p_wih_hi, *p_wih_lo, *p_a_hi, *p_a_lo;
    float *p_xproj, *p_out0, *p_out1;
    cudaGetSymbolAddress((void**)&p_dec_hi, g_dec_hi);
    cudaGetSymbolAddress((void**)&p_dec_lo, g_dec_lo);
    cudaGetSymbolAddress((void**)&p_wih_hi, g_wih_hi);
    cudaGetSymbolAddress((void**)&p_wih_lo, g_wih_lo);
    cudaGetSymbolAddress((void**)&p_a_hi,   g_a_hi);
    cudaGetSymbolAddress((void**)&p_a_lo,   g_a_lo);
    cudaGetSymbolAddress((void**)&p_xproj,  g_xproj);
    cudaGetSymbolAddress((void**)&p_out0,   g_out0);
    cudaGetSymbolAddress((void**)&p_out1,   g_out1);

    // weight conversions (fp32 -> bf16 hi/lo)
    split_kernel<<<8192, 256>>>((const float4*)decW, (ushort4*)p_dec_hi,
                                (ushort4*)p_dec_lo, (int)((size_t)V_ * H_ / 4));
    split_kernel<<<4096, 256>>>((const float4*)Wih, (ushort4*)p_wih_hi,
                                (ushort4*)p_wih_lo, (int)((size_t)L_ * G4H * H_ / 4));

    // embedding gather -> bf16 hi/lo
    embed_kernel<<<MROWS, 256>>>(input, embw);

    // layer 0: x_proj = emb @ Wih0^T + bih0 + bhh0
    {
        dim3 grid(MROWS / 128, G4H / 128);
        mma_gemm<<<grid, 256, GEMM_SMEM>>>(p_a_hi, p_a_lo, p_wih_hi, p_wih_lo,
                                           bih, bhh, p_xproj, G4H, H_);
    }
    rnn_init<<<32, 256>>>(h0);
    rnn_kernel<<<REC_CTAS, 256, RNN_SMEM>>>(Whh, p_xproj, c0, p_out0,
                                            out + HS_OFF, out + CS_OFF);

    // layer 1
    split_kernel<<<2048, 256>>>((const float4*)p_out0, (ushort4*)p_a_hi,
                                (ushort4*)p_a_lo, (int)((size_t)MROWS * H_ / 4));
    {
        dim3 grid(MROWS / 128, G4H / 128);
        mma_gemm<<<grid, 256, GEMM_SMEM>>>(p_a_hi, p_a_lo,
                                           p_wih_hi + (size_t)G4H * H_,
                                           p_wih_lo + (size_t)G4H * H_,
                                           bih + G4H, bhh + G4H, p_xproj, G4H, H_);
    }
    rnn_init<<<32, 256>>>(h0 + B_ * H_);
    rnn_kernel<<<REC_CTAS, 256, RNN_SMEM>>>(Whh + (size_t)G4H * H_, p_xproj,
                                            c0 + B_ * H_, p_out1,
                                            out + HS_OFF + B_ * H_,
                                            out + CS_OFF + B_ * H_);

    // decoder
    split_kernel<<<2048, 256>>>((const float4*)p_out1, (ushort4*)p_a_hi,
                                (ushort4*)p_a_lo, (int)((size_t)MROWS * H_ / 4));
    {
        dim3 grid(MROWS / 128, V_ / 128);
        mma_gemm<<<grid, 256, GEMM_SMEM>>>(p_a_hi, p_a_lo, p_dec_hi, p_dec_lo,
                                           decb, nullptr, out, V_, H_);
    }
}

// round 13
// speedup vs baseline: 1.3686x; 1.0271x over previous
#include <cuda_runtime.h>
#include <cuda_bf16.h>
#include <math.h>
#include <stdint.h>

// Problem constants
#define T_ 128
#define B_ 32
#define L_ 2
#define H_ 1024
#define E_ 1024
#define V_ 32000
#define G4H 4096
#define MROWS 4096
#define DEC_OFF ((size_t)T_ * B_ * V_)
#define HS_OFF  (DEC_OFF)
#define CS_OFF  (DEC_OFF + (size_t)L_ * B_ * H_)

// -------------------- scratch (static device memory) ------------------------
__device__ __nv_bfloat16 g_dec_hi[(size_t)V_ * H_];
__device__ __nv_bfloat16 g_dec_lo[(size_t)V_ * H_];
__device__ __nv_bfloat16 g_wih_hi[(size_t)L_ * G4H * H_];
__device__ __nv_bfloat16 g_wih_lo[(size_t)L_ * G4H * H_];
__device__ __nv_bfloat16 g_a_hi[(size_t)MROWS * H_];
__device__ __nv_bfloat16 g_a_lo[(size_t)MROWS * H_];
__device__ float g_xproj[(size_t)MROWS * G4H];
__device__ float g_out0 [(size_t)MROWS * H_];
__device__ float g_out1 [(size_t)MROWS * H_];
__device__ float g_hbuf [2][B_ * H_];
__device__ unsigned g_bar;

// ============================ helpers ========================================
__device__ __forceinline__ uint32_t smem_u32(const void* p){
    uint32_t a;
    asm("{ .reg .u64 t; cvta.to.shared.u64 t, %1; cvt.u32.u64 %0, t; }"
        : "=r"(a) : "l"(p));
    return a;
}
__device__ __forceinline__ void split1(float x, unsigned short &h, unsigned short &l){
    __nv_bfloat16 bh = __float2bfloat16(x);
    __nv_bfloat16 bl = __float2bfloat16(x - __bfloat162float(bh));
    h = *(unsigned short*)&bh;
    l = *(unsigned short*)&bl;
}
// packed f32x2 helpers (base sm_100+ PTX, not an 'a' feature)
__device__ __forceinline__ uint64_t pack2(float x){
    uint64_t r;
    asm("mov.b64 %0, {%1, %1};" : "=l"(r) : "f"(x));
    return r;
}
__device__ __forceinline__ void fma2(uint64_t &d, uint64_t a, uint64_t b){
    asm("fma.rn.f32x2 %0, %1, %2, %0;" : "+l"(d) : "l"(a), "l"(b));
}
__device__ __forceinline__ void unpack2(uint64_t v, float &lo, float &hi){
    asm("mov.b64 {%0, %1}, %2;" : "=f"(lo), "=f"(hi) : "l"(v));
}

// ======================= fp32 -> bf16 hi/lo conversion =======================
__global__ void split_kernel(const float4* __restrict__ src,
                             ushort4* __restrict__ hi, ushort4* __restrict__ lo,
                             int n4){
    for (int i = blockIdx.x * blockDim.x + threadIdx.x; i < n4;
         i += gridDim.x * blockDim.x){
        float4 v = src[i];
        ushort4 h, l;
        split1(v.x, h.x, l.x); split1(v.y, h.y, l.y);
        split1(v.z, h.z, l.z); split1(v.w, h.w, l.w);
        hi[i] = h; lo[i] = l;
    }
}

// ====================== embedding gather -> bf16 hi/lo =======================
__global__ void embed_kernel(const int* __restrict__ inp,
                             const float* __restrict__ embw){
    int row = blockIdx.x;
    int tok = inp[row];
    const float4* src = (const float4*)(embw + (size_t)tok * E_);
    ushort4* dh = (ushort4*)(g_a_hi + (size_t)row * E_);
    ushort4* dl = (ushort4*)(g_a_lo + (size_t)row * E_);
    float4 v = src[threadIdx.x];
    ushort4 h, l;
    split1(v.x, h.x, l.x); split1(v.y, h.y, l.y);
    split1(v.z, h.z, l.z); split1(v.w, h.w, l.w);
    dh[threadIdx.x] = h; dl[threadIdx.x] = l;
}

// ============ bf16-split NT GEMM via mma.sync (legacy HMMA path) =============
#define KS 64
#define TILE_B (128 * 128)
#define STAGE_B (4 * TILE_B)
#define GEMM_SMEM (2 * STAGE_B)

__device__ __forceinline__ uint32_t sw_addr(uint32_t base, int row, int chunk){
    return base + row * 128 + (((chunk ^ (row & 7)) & 7) << 4);
}
__device__ __forceinline__ void ldm_x4(uint32_t addr, uint32_t r[4]){
    asm volatile("ldmatrix.sync.aligned.m8n8.x4.shared.b16 {%0,%1,%2,%3}, [%4];"
                 : "=r"(r[0]), "=r"(r[1]), "=r"(r[2]), "=r"(r[3]) : "r"(addr));
}
__device__ __forceinline__ void mma16816(float c[4], const uint32_t a[4],
                                         const uint32_t b0, const uint32_t b1){
    asm volatile(
        "mma.sync.aligned.m16n8k16.row.col.f32.bf16.bf16.f32 "
        "{%0,%1,%2,%3}, {%4,%5,%6,%7}, {%8,%9}, {%0,%1,%2,%3};"
        : "+f"(c[0]), "+f"(c[1]), "+f"(c[2]), "+f"(c[3])
        : "r"(a[0]), "r"(a[1]), "r"(a[2]), "r"(a[3]), "r"(b0), "r"(b1));
}

__global__ __launch_bounds__(256, 1)
void mma_gemm(const __nv_bfloat16* __restrict__ Ahi,
              const __nv_bfloat16* __restrict__ Alo,
              const __nv_bfloat16* __restrict__ Bhi,
              const __nv_bfloat16* __restrict__ Blo,
              const float* __restrict__ b1, const float* __restrict__ b2,
              float* __restrict__ C, int N, int K)
{
    extern __shared__ char smem[];
    uint32_t sb = smem_u32(smem);
    int tid = threadIdx.x, wid = tid >> 5, lane = tid & 31;
    int bm = blockIdx.x * 128, bn = blockIdx.y * 128;
    int wm = wid & 1, wn = wid >> 1;

    float acc[4][4][4];
#pragma unroll
    for (int i = 0; i < 4; i++)
#pragma unroll
        for (int j = 0; j < 4; j++)
#pragma unroll
            for (int k = 0; k < 4; k++) acc[i][j][k] = 0.f;

    const int nst = K / KS;

#define LOAD_STAGE(s)                                                          \
    {                                                                          \
        uint32_t tb_ = sb + ((s) & 1) * STAGE_B;                               \
        for (int i = tid; i < 4096; i += 256){                                 \
            int tile = i >> 10, r = (i >> 3) & 127, seg = i & 7;               \
            const __nv_bfloat16* src = (tile == 0) ? Ahi : (tile == 1) ? Alo   \
                                     : (tile == 2) ? Bhi : Blo;                \
            int grow = ((tile < 2) ? bm : bn) + r;                             \
            const char* g = (const char*)(src + (size_t)grow * K + (s) * KS)   \
                            + seg * 16;                                        \
            uint32_t d = sw_addr(tb_ + tile * TILE_B, r, seg);                 \
            asm volatile("cp.async.cg.shared.global [%0], [%1], 16;"           \
                         :: "r"(d), "l"(g) : "memory");                        \
        }                                                                      \
        asm volatile("cp.async.commit_group;" ::: "memory");                   \
    }

    LOAD_STAGE(0);

    for (int s = 0; s < nst; s++){
        if (s + 1 < nst) LOAD_STAGE(s + 1);
        if (s + 1 < nst)
            asm volatile("cp.async.wait_group 1;" ::: "memory");
        else
            asm volatile("cp.async.wait_group 0;" ::: "memory");
        __syncthreads();

        uint32_t tb = sb + (s & 1) * STAGE_B;
        uint32_t a_hi_b = tb, a_lo_b = tb + TILE_B;
        uint32_t b_hi_b = tb + 2 * TILE_B, b_lo_b = tb + 3 * TILE_B;

#pragma unroll
        for (int k16 = 0; k16 < KS / 16; k16++){
            uint32_t ah[4][4], al[4][4], bh[4][2], bl[4][2];
            int ar = wm * 64 + (lane & 15);
            int ac = k16 * 2 + (lane >> 4);
#pragma unroll
            for (int mt = 0; mt < 4; mt++){
                ldm_x4(sw_addr(a_hi_b, ar + mt * 16, ac), ah[mt]);
                ldm_x4(sw_addr(a_lo_b, ar + mt * 16, ac), al[mt]);
            }
            int br = wn * 32 + (lane & 7) + ((lane >> 4) & 1) * 8;
            int bc = k16 * 2 + ((lane >> 3) & 1);
#pragma unroll
            for (int np = 0; np < 2; np++){
                uint32_t r4[4];
                ldm_x4(sw_addr(b_hi_b, br + np * 16, bc), r4);
                bh[np * 2][0] = r4[0]; bh[np * 2][1] = r4[1];
                bh[np * 2 + 1][0] = r4[2]; bh[np * 2 + 1][1] = r4[3];
                ldm_x4(sw_addr(b_lo_b, br + np * 16, bc), r4);
                bl[np * 2][0] = r4[0]; bl[np * 2][1] = r4[1];
                bl[np * 2 + 1][0] = r4[2]; bl[np * 2 + 1][1] = r4[3];
            }
#pragma unroll
            for (int mt = 0; mt < 4; mt++)
#pragma unroll
                for (int nt = 0; nt < 4; nt++){
                    mma16816(acc[mt][nt], ah[mt], bh[nt][0], bh[nt][1]);
                    mma16816(acc[mt][nt], ah[mt], bl[nt][0], bl[nt][1]);
                    mma16816(acc[mt][nt], al[mt], bh[nt][0], bh[nt][1]);
                }
        }
        __syncthreads();
    }

    int m0 = bm + wm * 64 + (lane >> 2);
    int n0 = bn + wn * 32 + (lane & 3) * 2;
#pragma unroll
    for (int nt = 0; nt < 4; nt++){
        int c = n0 + nt * 8;
        float bx = b1[c]     + (b2 ? b2[c]     : 0.f);
        float by = b1[c + 1] + (b2 ? b2[c + 1] : 0.f);
#pragma unroll
        for (int mt = 0; mt < 4; mt++){
            int r = m0 + mt * 16;
            float2 v0 = make_float2(acc[mt][nt][0] + bx, acc[mt][nt][1] + by);
            float2 v1 = make_float2(acc[mt][nt][2] + bx, acc[mt][nt][3] + by);
            *(float2*)&C[(size_t)r * N + c] = v0;
            *(float2*)&C[(size_t)(r + 8) * N + c] = v1;
        }
    }
#undef LOAD_STAGE
}

// ========================= LSTM recurrence (persistent) ======================
// 128 CTAs x 256 thr, 1 CTA/SM. Thread (b = tid>>3, jl = tid&7) computes the
// 4 gates of unit j = cta*8+jl for batch b. W in smem [jl][k][gate] so the
// per-k 4-gate row is one 16B LDS serving 2 packed f32x2 FMAs.
#define REC_CTAS 128
#define JPC 8
#define WROW 4100
#define RNN_SMEM (JPC * WROW * 4)

__global__ void rnn_init(const float* __restrict__ h0l)
{
    int i = blockIdx.x * blockDim.x + threadIdx.x;
    for (int k = i; k < B_ * H_; k += gridDim.x * blockDim.x)
        g_hbuf[0][k] = h0l[k];
    if (i == 0) g_bar = 0u;
}

__global__ __launch_bounds__(256, 1) void rnn_kernel(
    const float* __restrict__ Whh, const float* __restrict__ xproj,
    const float* __restrict__ c0l, float* __restrict__ layer_out,
    float* __restrict__ hs_out, float* __restrict__ cs_out)
{
    extern __shared__ float Wsm[];
    int tid = threadIdx.x;
    int cta = blockIdx.x;
    int b  = tid >> 3;
    int jl = tid & 7;
    int j  = cta * JPC + jl;

    for (int r = 0; r < 32; r++){
        int g = r >> 3, jl2 = r & 7;
        const float* src = Whh + (size_t)(g * H_ + cta * JPC + jl2) * H_;
        for (int k = tid; k < H_; k += 256)
            Wsm[jl2 * WROW + k * 4 + g] = src[k];
    }
    float c = c0l[b * H_ + j];
    __syncthreads();

    const ulonglong2* wrow = (const ulonglong2*)(Wsm + jl * WROW);
    unsigned* barp = &g_bar;

    for (int t = 0; t < T_; t++){
        const float4* hrow = (const float4*)(g_hbuf[t & 1] + b * H_);
        int m = t * B_ + b;
        const float* xp = xproj + (size_t)m * G4H;
        // hoist gate biases (independent LDGs, overlap with matvec)
        float x0 = xp[j], x1 = xp[H_ + j], x2 = xp[2 * H_ + j], x3 = xp[3 * H_ + j];

        uint64_t acc01 = pack2(0.f), acc23 = pack2(0.f);
#pragma unroll 8
        for (int k4 = 0; k4 < H_ / 4; k4++){
            float4 hv = __ldcg(&hrow[k4]);
            ulonglong2 w0 = wrow[k4 * 4 + 0];
            ulonglong2 w1 = wrow[k4 * 4 + 1];
            ulonglong2 w2 = wrow[k4 * 4 + 2];
            ulonglong2 w3 = wrow[k4 * 4 + 3];
            uint64_t h0 = pack2(hv.x), h1 = pack2(hv.y);
            uint64_t h2 = pack2(hv.z), h3 = pack2(hv.w);
            fma2(acc01, h0, w0.x); fma2(acc23, h0, w0.y);
            fma2(acc01, h1, w1.x); fma2(acc23, h1, w1.y);
            fma2(acc01, h2, w2.x); fma2(acc23, h2, w2.y);
            fma2(acc01, h3, w3.x); fma2(acc23, h3, w3.y);
        }
        float a0, a1, a2, a3;
        unpack2(acc01, a0, a1);
        unpack2(acc23, a2, a3);

        float gi = a0 + x0;
        float gf = a1 + x1;
        float gg = a2 + x2;
        float go = a3 + x3;
        float ig = 1.f / (1.f + expf(-gi));
        float fg = 1.f / (1.f + expf(-gf));
        float gt = tanhf(gg);
        float og = 1.f / (1.f + expf(-go));
        c = fg * c + ig * gt;
        float h = og * tanhf(c);

        g_hbuf[(t + 1) & 1][b * H_ + j] = h;
        layer_out[(size_t)m * H_ + j] = h;
        if (t == T_ - 1){ hs_out[b * H_ + j] = h; cs_out[b * H_ + j] = c; }

        if (t < T_ - 1){
            __threadfence();                       // release h writes
            __syncthreads();
            if (tid == 0){
                atomicAdd(barp, 1u);               // arrive
                unsigned target = (unsigned)(t + 1) * (unsigned)gridDim.x;
                unsigned v;
                do {                               // contention-free L2 poll
                    asm volatile("ld.acquire.gpu.global.u32 %0, [%1];"
                                 : "=r"(v) : "l"(barp) : "memory");
                } while (v < target);
            }
            __syncthreads();
        }
    }
}

// ================================ launch =====================================
extern "C" void kernel_launch(void* const* d_in, const int* in_sizes, int n_in,
                              void* d_out, int out_size)
{
    (void)in_sizes; (void)n_in; (void)out_size;
    const int*   input = (const int*)  d_in[0];
    const float* h0    = (const float*)d_in[1];
    const float* c0    = (const float*)d_in[2];
    const float* embw  = (const float*)d_in[3];
    const float* Wih   = (const float*)d_in[4];
    const float* Whh   = (const float*)d_in[5];
    const float* bih   = (const float*)d_in[6];
    const float* bhh   = (const float*)d_in[7];
    const float* decW  = (const float*)d_in[8];
    const float* decb  = (const float*)d_in[9];
    float* out = (float*)d_out;

    cudaFuncSetAttribute(rnn_kernel, cudaFuncAttributeMaxDynamicSharedMemorySize, RNN_SMEM);
    cudaFuncSetAttribute(mma_gemm,  cudaFuncAttributeMaxDynamicSharedMemorySize, GEMM_SMEM);

    __nv_bfloat16 *p_dec_hi, *p_dec_lo, *p_wih_hi, *p_wih_lo, *p_a_hi, *p_a_lo;
    float *p_xproj, *p_out0, *p_out1;
    cudaGetSymbolAddress((void**)&p_dec_hi, g_dec_hi);
    cudaGetSymbolAddress((void**)&p_dec_lo, g_dec_lo);
    cudaGetSymbolAddress((void**)&p_wih_hi, g_wih_hi);
    cudaGetSymbolAddress((void**)&p_wih_lo, g_wih_lo);
    cudaGetSymbolAddress((void**)&p_a_hi,   g_a_hi);
    cudaGetSymbolAddress((void**)&p_a_lo,   g_a_lo);
    cudaGetSymbolAddress((void**)&p_xproj,  g_xproj);
    cudaGetSymbolAddress((void**)&p_out0,   g_out0);
    cudaGetSymbolAddress((void**)&p_out1,   g_out1);

    // weight conversions (fp32 -> bf16 hi/lo)
    split_kernel<<<8192, 256>>>((const float4*)decW, (ushort4*)p_dec_hi,
                                (ushort4*)p_dec_lo, (int)((size_t)V_ * H_ / 4));
    split_kernel<<<4096, 256>>>((const float4*)Wih, (ushort4*)p_wih_hi,
                                (ushort4*)p_wih_lo, (int)((size_t)L_ * G4H * H_ / 4));

    // embedding gather -> bf16 hi/lo
    embed_kernel<<<MROWS, 256>>>(input, embw);

    // layer 0: x_proj = emb @ Wih0^T + bih0 + bhh0
    {
        dim3 grid(MROWS / 128, G4H / 128);
        mma_gemm<<<grid, 256, GEMM_SMEM>>>(p_a_hi, p_a_lo, p_wih_hi, p_wih_lo,
                                           bih, bhh, p_xproj, G4H, H_);
    }
    rnn_init<<<32, 256>>>(h0);
    rnn_kernel<<<REC_CTAS, 256, RNN_SMEM>>>(Whh, p_xproj, c0, p_out0,
                                            out + HS_OFF, out + CS_OFF);

    // layer 1
    split_kernel<<<2048, 256>>>((const float4*)p_out0, (ushort4*)p_a_hi,
                                (ushort4*)p_a_lo, (int)((size_t)MROWS * H_ / 4));
    {
        dim3 grid(MROWS / 128, G4H / 128);
        mma_gemm<<<grid, 256, GEMM_SMEM>>>(p_a_hi, p_a_lo,
                                           p_wih_hi + (size_t)G4H * H_,
                                           p_wih_lo + (size_t)G4H * H_,
                                           bih + G4H, bhh + G4H, p_xproj, G4H, H_);
    }
    rnn_init<<<32, 256>>>(h0 + B_ * H_);
    rnn_kernel<<<REC_CTAS, 256, RNN_SMEM>>>(Whh + (size_t)G4H * H_, p_xproj,
                                            c0 + B_ * H_, p_out1,
                                            out + HS_OFF + B_ * H_,
                                            out + CS_OFF + B_ * H_);

    // decoder
    split_kernel<<<2048, 256>>>((const float4*)p_out1, (ushort4*)p_a_hi,
                                (ushort4*)p_a_lo, (int)((size_t)MROWS * H_ / 4));
    {
        dim3 grid(MROWS / 128, V_ / 128);
        mma_gemm<<<grid, 256, GEMM_SMEM>>>(p_a_hi, p_a_lo, p_dec_hi, p_dec_lo,
                                           decb, nullptr, out, V_, H_);
    }
}

// round 14
// speedup vs baseline: 1.7479x; 1.2771x over previous
#include <cuda_runtime.h>
#include <cuda_bf16.h>
#include <math.h>
#include <stdint.h>

// Problem constants
#define T_ 128
#define B_ 32
#define L_ 2
#define H_ 1024
#define E_ 1024
#define V_ 32000
#define G4H 4096
#define MROWS 4096
#define DEC_OFF ((size_t)T_ * B_ * V_)
#define HS_OFF  (DEC_OFF)
#define CS_OFF  (DEC_OFF + (size_t)L_ * B_ * H_)

// -------------------- scratch (static device memory) ------------------------
__device__ __nv_bfloat16 g_dec_hi[(size_t)V_ * H_];
__device__ __nv_bfloat16 g_dec_lo[(size_t)V_ * H_];
__device__ __nv_bfloat16 g_wih_hi[(size_t)L_ * G4H * H_];
__device__ __nv_bfloat16 g_wih_lo[(size_t)L_ * G4H * H_];
__device__ __nv_bfloat16 g_a_hi[(size_t)MROWS * H_];
__device__ __nv_bfloat16 g_a_lo[(size_t)MROWS * H_];
__device__ float g_xproj[(size_t)MROWS * G4H];
__device__ float g_out0 [(size_t)MROWS * H_];
__device__ float g_out1 [(size_t)MROWS * H_];
__device__ float g_hbufT[2][H_][B_];          // transposed h state [buf][k][b]
__device__ unsigned g_bar;

// ============================ helpers ========================================
__device__ __forceinline__ uint32_t smem_u32(const void* p){
    uint32_t a;
    asm("{ .reg .u64 t; cvta.to.shared.u64 t, %1; cvt.u32.u64 %0, t; }"
        : "=r"(a) : "l"(p));
    return a;
}
__device__ __forceinline__ void split1(float x, unsigned short &h, unsigned short &l){
    __nv_bfloat16 bh = __float2bfloat16(x);
    __nv_bfloat16 bl = __float2bfloat16(x - __bfloat162float(bh));
    h = *(unsigned short*)&bh;
    l = *(unsigned short*)&bl;
}
// packed f32x2 helpers (base sm_100+ PTX)
__device__ __forceinline__ uint64_t pack2(float x){
    uint64_t r;
    asm("mov.b64 %0, {%1, %1};" : "=l"(r) : "f"(x));
    return r;
}
__device__ __forceinline__ void fma2(uint64_t &d, uint64_t a, uint64_t b){
    asm("fma.rn.f32x2 %0, %1, %2, %0;" : "+l"(d) : "l"(a), "l"(b));
}
__device__ __forceinline__ void unpack2(uint64_t v, float &lo, float &hi){
    asm("mov.b64 {%0, %1}, %2;" : "=f"(lo), "=f"(hi) : "l"(v));
}

// ======================= fp32 -> bf16 hi/lo conversion =======================
__global__ void split_kernel(const float4* __restrict__ src,
                             ushort4* __restrict__ hi, ushort4* __restrict__ lo,
                             int n4){
    for (int i = blockIdx.x * blockDim.x + threadIdx.x; i < n4;
         i += gridDim.x * blockDim.x){
        float4 v = src[i];
        ushort4 h, l;
        split1(v.x, h.x, l.x); split1(v.y, h.y, l.y);
        split1(v.z, h.z, l.z); split1(v.w, h.w, l.w);
        hi[i] = h; lo[i] = l;
    }
}

// ====================== embedding gather -> bf16 hi/lo =======================
__global__ void embed_kernel(const int* __restrict__ inp,
                             const float* __restrict__ embw){
    int row = blockIdx.x;
    int tok = inp[row];
    const float4* src = (const float4*)(embw + (size_t)tok * E_);
    ushort4* dh = (ushort4*)(g_a_hi + (size_t)row * E_);
    ushort4* dl = (ushort4*)(g_a_lo + (size_t)row * E_);
    float4 v = src[threadIdx.x];
    ushort4 h, l;
    split1(v.x, h.x, l.x); split1(v.y, h.y, l.y);
    split1(v.z, h.z, l.z); split1(v.w, h.w, l.w);
    dh[threadIdx.x] = h; dl[threadIdx.x] = l;
}

// ============ bf16-split NT GEMM via mma.sync (legacy HMMA path) =============
#define KS 64
#define TILE_B (128 * 128)
#define STAGE_B (4 * TILE_B)
#define GEMM_SMEM (2 * STAGE_B)

__device__ __forceinline__ uint32_t sw_addr(uint32_t base, int row, int chunk){
    return base + row * 128 + (((chunk ^ (row & 7)) & 7) << 4);
}
__device__ __forceinline__ void ldm_x4(uint32_t addr, uint32_t r[4]){
    asm volatile("ldmatrix.sync.aligned.m8n8.x4.shared.b16 {%0,%1,%2,%3}, [%4];"
                 : "=r"(r[0]), "=r"(r[1]), "=r"(r[2]), "=r"(r[3]) : "r"(addr));
}
__device__ __forceinline__ void mma16816(float c[4], const uint32_t a[4],
                                         const uint32_t b0, const uint32_t b1){
    asm volatile(
        "mma.sync.aligned.m16n8k16.row.col.f32.bf16.bf16.f32 "
        "{%0,%1,%2,%3}, {%4,%5,%6,%7}, {%8,%9}, {%0,%1,%2,%3};"
        : "+f"(c[0]), "+f"(c[1]), "+f"(c[2]), "+f"(c[3])
        : "r"(a[0]), "r"(a[1]), "r"(a[2]), "r"(a[3]), "r"(b0), "r"(b1));
}

__global__ __launch_bounds__(256, 1)
void mma_gemm(const __nv_bfloat16* __restrict__ Ahi,
              const __nv_bfloat16* __restrict__ Alo,
              const __nv_bfloat16* __restrict__ Bhi,
              const __nv_bfloat16* __restrict__ Blo,
              const float* __restrict__ b1, const float* __restrict__ b2,
              float* __restrict__ C, int N, int K)
{
    extern __shared__ char smem[];
    uint32_t sb = smem_u32(smem);
    int tid = threadIdx.x, wid = tid >> 5, lane = tid & 31;
    int bm = blockIdx.x * 128, bn = blockIdx.y * 128;
    int wm = wid & 1, wn = wid >> 1;

    float acc[4][4][4];
#pragma unroll
    for (int i = 0; i < 4; i++)
#pragma unroll
        for (int j = 0; j < 4; j++)
#pragma unroll
            for (int k = 0; k < 4; k++) acc[i][j][k] = 0.f;

    const int nst = K / KS;

#define LOAD_STAGE(s)                                                          \
    {                                                                          \
        uint32_t tb_ = sb + ((s) & 1) * STAGE_B;                               \
        for (int i = tid; i < 4096; i += 256){                                 \
            int tile = i >> 10, r = (i >> 3) & 127, seg = i & 7;               \
            const __nv_bfloat16* src = (tile == 0) ? Ahi : (tile == 1) ? Alo   \
                                     : (tile == 2) ? Bhi : Blo;                \
            int grow = ((tile < 2) ? bm : bn) + r;                             \
            const char* g = (const char*)(src + (size_t)grow * K + (s) * KS)   \
                            + seg * 16;                                        \
            uint32_t d = sw_addr(tb_ + tile * TILE_B, r, seg);                 \
            asm volatile("cp.async.cg.shared.global [%0], [%1], 16;"           \
                         :: "r"(d), "l"(g) : "memory");                        \
        }                                                                      \
        asm volatile("cp.async.commit_group;" ::: "memory");                   \
    }

    LOAD_STAGE(0);

    for (int s = 0; s < nst; s++){
        if (s + 1 < nst) LOAD_STAGE(s + 1);
        if (s + 1 < nst)
            asm volatile("cp.async.wait_group 1;" ::: "memory");
        else
            asm volatile("cp.async.wait_group 0;" ::: "memory");
        __syncthreads();

        uint32_t tb = sb + (s & 1) * STAGE_B;
        uint32_t a_hi_b = tb, a_lo_b = tb + TILE_B;
        uint32_t b_hi_b = tb + 2 * TILE_B, b_lo_b = tb + 3 * TILE_B;

#pragma unroll
        for (int k16 = 0; k16 < KS / 16; k16++){
            uint32_t ah[4][4], al[4][4], bh[4][2], bl[4][2];
            int ar = wm * 64 + (lane & 15);
            int ac = k16 * 2 + (lane >> 4);
#pragma unroll
            for (int mt = 0; mt < 4; mt++){
                ldm_x4(sw_addr(a_hi_b, ar + mt * 16, ac), ah[mt]);
                ldm_x4(sw_addr(a_lo_b, ar + mt * 16, ac), al[mt]);
            }
            int br = wn * 32 + (lane & 7) + ((lane >> 4) & 1) * 8;
            int bc = k16 * 2 + ((lane >> 3) & 1);
#pragma unroll
            for (int np = 0; np < 2; np++){
                uint32_t r4[4];
                ldm_x4(sw_addr(b_hi_b, br + np * 16, bc), r4);
                bh[np * 2][0] = r4[0]; bh[np * 2][1] = r4[1];
                bh[np * 2 + 1][0] = r4[2]; bh[np * 2 + 1][1] = r4[3];
                ldm_x4(sw_addr(b_lo_b, br + np * 16, bc), r4);
                bl[np * 2][0] = r4[0]; bl[np * 2][1] = r4[1];
                bl[np * 2 + 1][0] = r4[2]; bl[np * 2 + 1][1] = r4[3];
            }
#pragma unroll
            for (int mt = 0; mt < 4; mt++)
#pragma unroll
                for (int nt = 0; nt < 4; nt++){
                    mma16816(acc[mt][nt], ah[mt], bh[nt][0], bh[nt][1]);
                    mma16816(acc[mt][nt], ah[mt], bl[nt][0], bl[nt][1]);
                    mma16816(acc[mt][nt], al[mt], bh[nt][0], bh[nt][1]);
                }
        }
        __syncthreads();
    }

    int m0 = bm + wm * 64 + (lane >> 2);
    int n0 = bn + wn * 32 + (lane & 3) * 2;
#pragma unroll
    for (int nt = 0; nt < 4; nt++){
        int c = n0 + nt * 8;
        float bx = b1[c]     + (b2 ? b2[c]     : 0.f);
        float by = b1[c + 1] + (b2 ? b2[c + 1] : 0.f);
#pragma unroll
        for (int mt = 0; mt < 4; mt++){
            int r = m0 + mt * 16;
            float2 v0 = make_float2(acc[mt][nt][0] + bx, acc[mt][nt][1] + by);
            float2 v1 = make_float2(acc[mt][nt][2] + bx, acc[mt][nt][3] + by);
            *(float2*)&C[(size_t)r * N + c] = v0;
            *(float2*)&C[(size_t)(r + 8) * N + c] = v1;
        }
    }
#undef LOAD_STAGE
}

// ========================= LSTM recurrence (persistent) ======================
// 128 CTAs x 256 thr, 1 CTA/SM, CTA owns 8 hidden units (jl).
// Matvec role: thread (kseg = tid>>5, jl = lane&7, bsub = lane>>3) computes
// partial gate sums over k in [kseg*128, +128) for 8 batches (bsub*8..+7).
// h is stored transposed hT[k][b] so batch-pairs load as packed f32x2.
// Per k: 1 LDS.128 (W row, 8-distinct/4-way bcast) + 2 LDG.128 (h pairs)
// + 4 dup-movs + 16 fma2. Cross-kseg reduction via smem partials, then
// activation role: thread (b = tid>>3, jl = tid&7) owns (b, j) and c-state.
#define REC_CTAS 128
#define JPC 8
#define WROW 4100
#define PART_OFF (JPC * WROW)                     // floats
#define PART_FLOATS (8 * 32 * 8 * 4)              // jl, b, kseg, gate = 8192
#define RNN_SMEM ((PART_OFF + PART_FLOATS) * 4)   // 131200 + 32768 B

__global__ void rnn_init(const float* __restrict__ h0l)
{
    int i = blockIdx.x * blockDim.x + threadIdx.x;
    for (int idx = i; idx < B_ * H_; idx += gridDim.x * blockDim.x){
        int b = idx & 31, k = idx >> 5;
        g_hbufT[0][k][b] = h0l[b * H_ + k];
    }
    if (i == 0) g_bar = 0u;
}

__global__ __launch_bounds__(256, 1) void rnn_kernel(
    const float* __restrict__ Whh, const float* __restrict__ xproj,
    const float* __restrict__ c0l, float* __restrict__ layer_out,
    float* __restrict__ hs_out, float* __restrict__ cs_out)
{
    extern __shared__ float Wsm[];
    float* Part = Wsm + PART_OFF;
    int tid = threadIdx.x;
    int cta = blockIdx.x;
    int lane = tid & 31;
    int kseg = tid >> 5;          // matvec: k-segment (warp id)
    int jlm  = lane & 7;          // matvec: unit within CTA
    int bsub = lane >> 3;         // matvec: batch octet
    int ab = tid >> 3;            // activation: batch
    int aj = tid & 7;             // activation: unit
    int j  = cta * JPC + aj;

    // load W_hh slice: Wsm[jl][k*4 + gate]
    for (int r = 0; r < 32; r++){
        int g = r >> 3, jl2 = r & 7;
        const float* src = Whh + (size_t)(g * H_ + cta * JPC + jl2) * H_;
        for (int k = tid; k < H_; k += 256)
            Wsm[jl2 * WROW + k * 4 + g] = src[k];
    }
    float c = c0l[ab * H_ + j];
    __syncthreads();

    const float* wrow = Wsm + jlm * WROW;
    const int b0 = bsub * 8;
    const int kbase = kseg * 128;
    unsigned* barp = &g_bar;

    for (int t = 0; t < T_; t++){
        const float* hT = &g_hbufT[t & 1][0][0];
        // activation-role operands (hidden under matvec)
        int m = t * B_ + ab;
        const float* xp = xproj + (size_t)m * G4H;
        float x0 = xp[j], x1 = xp[H_ + j], x2 = xp[2 * H_ + j], x3 = xp[3 * H_ + j];

        uint64_t acc[4][4];
#pragma unroll
        for (int bp = 0; bp < 4; bp++)
#pragma unroll
            for (int g = 0; g < 4; g++) acc[bp][g] = 0ull;

#pragma unroll 4
        for (int kk = 0; kk < 128; kk++){
            int k = kbase + kk;
            const float* hk = hT + k * B_ + b0;
            ulonglong2 hA = __ldcg((const ulonglong2*)hk);        // b0..b3 pairs
            ulonglong2 hB = __ldcg((const ulonglong2*)(hk + 4));  // b4..b7 pairs
            float4 wv = *(const float4*)(wrow + k * 4);
            uint64_t w0 = pack2(wv.x), w1 = pack2(wv.y);
            uint64_t w2 = pack2(wv.z), w3 = pack2(wv.w);
            fma2(acc[0][0], hA.x, w0); fma2(acc[0][1], hA.x, w1);
            fma2(acc[0][2], hA.x, w2); fma2(acc[0][3], hA.x, w3);
            fma2(acc[1][0], hA.y, w0); fma2(acc[1][1], hA.y, w1);
            fma2(acc[1][2], hA.y, w2); fma2(acc[1][3], hA.y, w3);
            fma2(acc[2][0], hB.x, w0); fma2(acc[2][1], hB.x, w1);
            fma2(acc[2][2], hB.x, w2); fma2(acc[2][3], hB.x, w3);
            fma2(acc[3][0], hB.y, w0); fma2(acc[3][1], hB.y, w1);
            fma2(acc[3][2], hB.y, w2); fma2(acc[3][3], hB.y, w3);
        }

        // write partials: Part[((jl*32 + b)*8 + kseg)*4 + g]
#pragma unroll
        for (int bp = 0; bp < 4; bp++){
            float4 pe, po;
            unpack2(acc[bp][0], pe.x, po.x);
            unpack2(acc[bp][1], pe.y, po.y);
            unpack2(acc[bp][2], pe.z, po.z);
            unpack2(acc[bp][3], pe.w, po.w);
            int be = b0 + bp * 2;
            *(float4*)&Part[((jlm * 32 + be) * 8 + kseg) * 4] = pe;
            *(float4*)&Part[((jlm * 32 + be + 1) * 8 + kseg) * 4] = po;
        }
        __syncthreads();

        // activation: reduce 8 ksegs for (ab, aj)
        const float4* prow = (const float4*)&Part[(aj * 32 + ab) * 8 * 4];
        float4 s = prow[0];
#pragma unroll
        for (int ks = 1; ks < 8; ks++){
            float4 p = prow[ks];
            s.x += p.x; s.y += p.y; s.z += p.z; s.w += p.w;
        }
        float gi = s.x + x0;
        float gf = s.y + x1;
        float gg = s.z + x2;
        float go = s.w + x3;
        float ig = 1.f / (1.f + expf(-gi));
        float fg = 1.f / (1.f + expf(-gf));
        float gt = tanhf(gg);
        float og = 1.f / (1.f + expf(-go));
        c = fg * c + ig * gt;
        float h = og * tanhf(c);

        g_hbufT[(t + 1) & 1][j][ab] = h;
        layer_out[(size_t)m * H_ + j] = h;
        if (t == T_ - 1){ hs_out[ab * H_ + j] = h; cs_out[ab * H_ + j] = c; }

        __threadfence();                      // publish h (and order Part reuse)
        __syncthreads();
        if (t < T_ - 1){
            if (tid == 0){
                atomicAdd(barp, 1u);
                unsigned target = (unsigned)(t + 1) * (unsigned)gridDim.x;
                unsigned v;
                do {
                    asm volatile("ld.acquire.gpu.global.u32 %0, [%1];"
                                 : "=r"(v) : "l"(barp) : "memory");
                } while (v < target);
            }
            __syncthreads();
        }
    }
}

// ================================ launch =====================================
extern "C" void kernel_launch(void* const* d_in, const int* in_sizes, int n_in,
                              void* d_out, int out_size)
{
    (void)in_sizes; (void)n_in; (void)out_size;
    const int*   input = (const int*)  d_in[0];
    const float* h0    = (const float*)d_in[1];
    const float* c0    = (const float*)d_in[2];
    const float* embw  = (const float*)d_in[3];
    const float* Wih   = (const float*)d_in[4];
    const float* Whh   = (const float*)d_in[5];
    const float* bih   = (const float*)d_in[6];
    const float* bhh   = (const float*)d_in[7];
    const float* decW  = (const float*)d_in[8];
    const float* decb  = (const float*)d_in[9];
    float* out = (float*)d_out;

    cudaFuncSetAttribute(rnn_kernel, cudaFuncAttributeMaxDynamicSharedMemorySize, RNN_SMEM);
    cudaFuncSetAttribute(mma_gemm,  cudaFuncAttributeMaxDynamicSharedMemorySize, GEMM_SMEM);

    __nv_bfloat16 *p_dec_hi, *p_dec_lo, *p_wih_hi, *p_wih_lo, *p_a_hi, *p_a_lo;
    float *p_xproj, *p_out0, *p_out1;
    cudaGetSymbolAddress((void**)&p_dec_hi, g_dec_hi);
    cudaGetSymbolAddress((void**)&p_dec_lo, g_dec_lo);
    cudaGetSymbolAddress((void**)&p_wih_hi, g_wih_hi);
    cudaGetSymbolAddress((void**)&p_wih_lo, g_wih_lo);
    cudaGetSymbolAddress((void**)&p_a_hi,   g_a_hi);
    cudaGetSymbolAddress((void**)&p_a_lo,   g_a_lo);
    cudaGetSymbolAddress((void**)&p_xproj,  g_xproj);
    cudaGetSymbolAddress((void**)&p_out0,   g_out0);
    cudaGetSymbolAddress((void**)&p_out1,   g_out1);

    // weight conversions (fp32 -> bf16 hi/lo)
    split_kernel<<<8192, 256>>>((const float4*)decW, (ushort4*)p_dec_hi,
                                (ushort4*)p_dec_lo, (int)((size_t)V_ * H_ / 4));
    split_kernel<<<4096, 256>>>((const float4*)Wih, (ushort4*)p_wih_hi,
                                (ushort4*)p_wih_lo, (int)((size_t)L_ * G4H * H_ / 4));

    // embedding gather -> bf16 hi/lo
    embed_kernel<<<MROWS, 256>>>(input, embw);

    // layer 0: x_proj = emb @ Wih0^T + bih0 + bhh0
    {
        dim3 grid(MROWS / 128, G4H / 128);
        mma_gemm<<<grid, 256, GEMM_SMEM>>>(p_a_hi, p_a_lo, p_wih_hi, p_wih_lo,
                                           bih, bhh, p_xproj, G4H, H_);
    }
    rnn_init<<<32, 256>>>(h0);
    rnn_kernel<<<REC_CTAS, 256, RNN_SMEM>>>(Whh, p_xproj, c0, p_out0,
                                            out + HS_OFF, out + CS_OFF);

    // layer 1
    split_kernel<<<2048, 256>>>((const float4*)p_out0, (ushort4*)p_a_hi,
                                (ushort4*)p_a_lo, (int)((size_t)MROWS * H_ / 4));
    {
        dim3 grid(MROWS / 128, G4H / 128);
        mma_gemm<<<grid, 256, GEMM_SMEM>>>(p_a_hi, p_a_lo,
                                           p_wih_hi + (size_t)G4H * H_,
                                           p_wih_lo + (size_t)G4H * H_,
                                           bih + G4H, bhh + G4H, p_xproj, G4H, H_);
    }
    rnn_init<<<32, 256>>>(h0 + B_ * H_);
    rnn_kernel<<<REC_CTAS, 256, RNN_SMEM>>>(Whh + (size_t)G4H * H_, p_xproj,
                                            c0 + B_ * H_, p_out1,
                                            out + HS_OFF + B_ * H_,
                                            out + CS_OFF + B_ * H_);

    // decoder
    split_kernel<<<2048, 256>>>((const float4*)p_out1, (ushort4*)p_a_hi,
                                (ushort4*)p_a_lo, (int)((size_t)MROWS * H_ / 4));
    {
        dim3 grid(MROWS / 128, V_ / 128);
        mma_gemm<<<grid, 256, GEMM_SMEM>>>(p_a_hi, p_a_lo, p_dec_hi, p_dec_lo,
                                           decb, nullptr, out, V_, H_);
    }
}

// round 16
// speedup vs baseline: 2.7100x; 1.5504x over previous
#include <cuda_runtime.h>
#include <cuda_bf16.h>
#include <math.h>
#include <stdint.h>

// Problem constants
#define T_ 128
#define B_ 32
#define L_ 2
#define H_ 1024
#define E_ 1024
#define V_ 32000
#define G4H 4096
#define MROWS 4096
#define DEC_OFF ((size_t)T_ * B_ * V_)
#define HS_OFF  (DEC_OFF)
#define CS_OFF  (DEC_OFF + (size_t)L_ * B_ * H_)

// -------------------- scratch (static device memory) ------------------------
__device__ __nv_bfloat16 g_dec_hi[(size_t)V_ * H_];
__device__ __nv_bfloat16 g_dec_lo[(size_t)V_ * H_];
__device__ __nv_bfloat16 g_wih_hi[(size_t)L_ * G4H * H_];
__device__ __nv_bfloat16 g_wih_lo[(size_t)L_ * G4H * H_];
__device__ __nv_bfloat16 g_a_hi[(size_t)MROWS * H_];
__device__ __nv_bfloat16 g_a_lo[(size_t)MROWS * H_];
__device__ float g_xproj[(size_t)MROWS * G4H];
__device__ float g_out0 [(size_t)MROWS * H_];
__device__ float g_out1 [(size_t)MROWS * H_];
// W_hh pre-split per CTA: [L][128 cta][2 ver][16 chunk][32 n][64 k] bf16
__device__ __nv_bfloat16 g_wsplit[(size_t)L_ * 128 * 2 * 16 * 32 * 64];
// h split state: [2 buf][2 ver][16 chunk][32 b][64 k] bf16
__device__ __nv_bfloat16 g_hsplit[2][2 * 16 * 32 * 64];
__device__ unsigned g_bar;

// ============================ helpers ========================================
__device__ __forceinline__ uint32_t smem_u32(const void* p){
    uint32_t a;
    asm("{ .reg .u64 t; cvta.to.shared.u64 t, %1; cvt.u32.u64 %0, t; }"
        : "=r"(a) : "l"(p));
    return a;
}
__device__ __forceinline__ void split1(float x, unsigned short &h, unsigned short &l){
    __nv_bfloat16 bh = __float2bfloat16(x);
    __nv_bfloat16 bl = __float2bfloat16(x - __bfloat162float(bh));
    h = *(unsigned short*)&bh;
    l = *(unsigned short*)&bl;
}
__device__ __forceinline__ uint32_t sw_addr(uint32_t base, int row, int chunk){
    return base + row * 128 + (((chunk ^ (row & 7)) & 7) << 4);
}
__device__ __forceinline__ void ldm_x4(uint32_t addr, uint32_t r[4]){
    asm volatile("ldmatrix.sync.aligned.m8n8.x4.shared.b16 {%0,%1,%2,%3}, [%4];"
                 : "=r"(r[0]), "=r"(r[1]), "=r"(r[2]), "=r"(r[3]) : "r"(addr));
}
__device__ __forceinline__ void mma16816(float c[4], const uint32_t a[4],
                                         const uint32_t b0, const uint32_t b1){
    asm volatile(
        "mma.sync.aligned.m16n8k16.row.col.f32.bf16.bf16.f32 "
        "{%0,%1,%2,%3}, {%4,%5,%6,%7}, {%8,%9}, {%0,%1,%2,%3};"
        : "+f"(c[0]), "+f"(c[1]), "+f"(c[2]), "+f"(c[3])
        : "r"(a[0]), "r"(a[1]), "r"(a[2]), "r"(a[3]), "r"(b0), "r"(b1));
}
__device__ __forceinline__ void cp16(uint32_t d, const void* g){
    asm volatile("cp.async.cg.shared.global [%0], [%1], 16;"
                 :: "r"(d), "l"(g) : "memory");
}

// ======================= fp32 -> bf16 hi/lo conversion =======================
__global__ void split_kernel(const float4* __restrict__ src,
                             ushort4* __restrict__ hi, ushort4* __restrict__ lo,
                             int n4){
    for (int i = blockIdx.x * blockDim.x + threadIdx.x; i < n4;
         i += gridDim.x * blockDim.x){
        float4 v = src[i];
        ushort4 h, l;
        split1(v.x, h.x, l.x); split1(v.y, h.y, l.y);
        split1(v.z, h.z, l.z); split1(v.w, h.w, l.w);
        hi[i] = h; lo[i] = l;
    }
}

// =========== W_hh split + relayout for tensor-core recurrence ================
// src Whh [L][4H][H] -> g_wsplit [(l*128+cta)][ver][chunk][n=g*8+jl][kk]
__global__ void wsplit_kernel(const float* __restrict__ Whh){
    const int total = L_ * G4H * H_;
    for (int i = blockIdx.x * blockDim.x + threadIdx.x; i < total;
         i += gridDim.x * blockDim.x){
        int l = i >> 22;
        int rem = i & 4194303;
        int row = rem >> 10;          // 0..4095 within layer
        int k = rem & 1023;
        float v = Whh[i];
        unsigned short hs, ls;
        split1(v, hs, ls);
        int g = row >> 10, rr = row & 1023;
        int cta = rr >> 3, jl = rr & 7;
        int n = g * 8 + jl;
        size_t base = ((size_t)(l * 128 + cta)) * 65536;
        size_t idx = base + ((size_t)(k >> 6)) * 2048 + n * 64 + (k & 63);
        *(unsigned short*)&g_wsplit[idx] = hs;                 // ver 0
        *(unsigned short*)&g_wsplit[idx + 32768] = ls;         // ver 1
    }
}

// ====================== embedding gather -> bf16 hi/lo =======================
__global__ void embed_kernel(const int* __restrict__ inp,
                             const float* __restrict__ embw){
    int row = blockIdx.x;
    int tok = inp[row];
    const float4* src = (const float4*)(embw + (size_t)tok * E_);
    ushort4* dh = (ushort4*)(g_a_hi + (size_t)row * E_);
    ushort4* dl = (ushort4*)(g_a_lo + (size_t)row * E_);
    float4 v = src[threadIdx.x];
    ushort4 h, l;
    split1(v.x, h.x, l.x); split1(v.y, h.y, l.y);
    split1(v.z, h.z, l.z); split1(v.w, h.w, l.w);
    dh[threadIdx.x] = h; dl[threadIdx.x] = l;
}

// ============ bf16-split NT GEMM via mma.sync (legacy HMMA path) =============
#define KS 64
#define TILE_B (128 * 128)
#define STAGE_B (4 * TILE_B)
#define GEMM_SMEM (2 * STAGE_B)

__global__ __launch_bounds__(256, 1)
void mma_gemm(const __nv_bfloat16* __restrict__ Ahi,
              const __nv_bfloat16* __restrict__ Alo,
              const __nv_bfloat16* __restrict__ Bhi,
              const __nv_bfloat16* __restrict__ Blo,
              const float* __restrict__ b1, const float* __restrict__ b2,
              float* __restrict__ C, int N, int K)
{
    extern __shared__ char smem[];
    uint32_t sb = smem_u32(smem);
    int tid = threadIdx.x, wid = tid >> 5, lane = tid & 31;
    int bm = blockIdx.x * 128, bn = blockIdx.y * 128;
    int wm = wid & 1, wn = wid >> 1;

    float acc[4][4][4];
#pragma unroll
    for (int i = 0; i < 4; i++)
#pragma unroll
        for (int j = 0; j < 4; j++)
#pragma unroll
            for (int k = 0; k < 4; k++) acc[i][j][k] = 0.f;

    const int nst = K / KS;

#define LOAD_STAGE(s)                                                          \
    {                                                                          \
        uint32_t tb_ = sb + ((s) & 1) * STAGE_B;                               \
        for (int i = tid; i < 4096; i += 256){                                 \
            int tile = i >> 10, r = (i >> 3) & 127, seg = i & 7;               \
            const __nv_bfloat16* src = (tile == 0) ? Ahi : (tile == 1) ? Alo   \
                                     : (tile == 2) ? Bhi : Blo;                \
            int grow = ((tile < 2) ? bm : bn) + r;                             \
            const char* g = (const char*)(src + (size_t)grow * K + (s) * KS)   \
                            + seg * 16;                                        \
            uint32_t d = sw_addr(tb_ + tile * TILE_B, r, seg);                 \
            cp16(d, g);                                                        \
        }                                                                      \
        asm volatile("cp.async.commit_group;" ::: "memory");                   \
    }

    LOAD_STAGE(0);

    for (int s = 0; s < nst; s++){
        if (s + 1 < nst) LOAD_STAGE(s + 1);
        if (s + 1 < nst)
            asm volatile("cp.async.wait_group 1;" ::: "memory");
        else
            asm volatile("cp.async.wait_group 0;" ::: "memory");
        __syncthreads();

        uint32_t tb = sb + (s & 1) * STAGE_B;
        uint32_t a_hi_b = tb, a_lo_b = tb + TILE_B;
        uint32_t b_hi_b = tb + 2 * TILE_B, b_lo_b = tb + 3 * TILE_B;

#pragma unroll
        for (int k16 = 0; k16 < KS / 16; k16++){
            uint32_t ah[4][4], al[4][4], bh[4][2], bl[4][2];
            int ar = wm * 64 + (lane & 15);
            int ac = k16 * 2 + (lane >> 4);
#pragma unroll
            for (int mt = 0; mt < 4; mt++){
                ldm_x4(sw_addr(a_hi_b, ar + mt * 16, ac), ah[mt]);
                ldm_x4(sw_addr(a_lo_b, ar + mt * 16, ac), al[mt]);
            }
            int br = wn * 32 + (lane & 7) + ((lane >> 4) & 1) * 8;
            int bc = k16 * 2 + ((lane >> 3) & 1);
#pragma unroll
            for (int np = 0; np < 2; np++){
                uint32_t r4[4];
                ldm_x4(sw_addr(b_hi_b, br + np * 16, bc), r4);
                bh[np * 2][0] = r4[0]; bh[np * 2][1] = r4[1];
                bh[np * 2 + 1][0] = r4[2]; bh[np * 2 + 1][1] = r4[3];
                ldm_x4(sw_addr(b_lo_b, br + np * 16, bc), r4);
                bl[np * 2][0] = r4[0]; bl[np * 2][1] = r4[1];
                bl[np * 2 + 1][0] = r4[2]; bl[np * 2 + 1][1] = r4[3];
            }
            // pass-major order: acc reuse distance = 16 (no RAW stalls)
#pragma unroll
            for (int mt = 0; mt < 4; mt++)
#pragma unroll
                for (int nt = 0; nt < 4; nt++)
                    mma16816(acc[mt][nt], ah[mt], bh[nt][0], bh[nt][1]);
#pragma unroll
            for (int mt = 0; mt < 4; mt++)
#pragma unroll
                for (int nt = 0; nt < 4; nt++)
                    mma16816(acc[mt][nt], ah[mt], bl[nt][0], bl[nt][1]);
#pragma unroll
            for (int mt = 0; mt < 4; mt++)
#pragma unroll
                for (int nt = 0; nt < 4; nt++)
                    mma16816(acc[mt][nt], al[mt], bh[nt][0], bh[nt][1]);
        }
        __syncthreads();
    }

    int m0 = bm + wm * 64 + (lane >> 2);
    int n0 = bn + wn * 32 + (lane & 3) * 2;
#pragma unroll
    for (int nt = 0; nt < 4; nt++){
        int c = n0 + nt * 8;
        float bx = b1[c]     + (b2 ? b2[c]     : 0.f);
        float by = b1[c + 1] + (b2 ? b2[c + 1] : 0.f);
#pragma unroll
        for (int mt = 0; mt < 4; mt++){
            int r = m0 + mt * 16;
            float2 v0 = make_float2(acc[mt][nt][0] + bx, acc[mt][nt][1] + by);
            float2 v1 = make_float2(acc[mt][nt][2] + bx, acc[mt][nt][3] + by);
            *(float2*)&C[(size_t)r * N + c] = v0;
            *(float2*)&C[(size_t)(r + 8) * N + c] = v1;
        }
    }
#undef LOAD_STAGE
}

// ================== LSTM recurrence (persistent, tensor-core) ================
// 128 CTAs x 256 thr, 1 CTA/SM. CTA owns 8 units j = cta*8 + jl, i.e. the 32
// Whh rows n = g*8+jl, held in smem as bf16 hi/lo [ver][16 chunk][32 n][64 k].
// Per step: D[32 b][32 n] = h[32 b][1024] @ W^T via m16n8k16, 3 split passes.
// h lives in gmem as split bf16 [buf][ver][chunk][b][64k], staged per K-quarter
// by cp.async (double buffered, overlapped with MMA of previous quarter).
// Warp (mt, np, kg) = (wid&1, (wid>>1)&1, wid>>2): m16 tile, gate pair, k half.
// Each n8 tile is exactly one gate. Partials reduced over kg via smem.
#define REC_CTAS 128
#define RNN_WBYTES (2 * 16 * 32 * 128)      // 131072
#define RNN_AOFF   RNN_WBYTES
#define RNN_ABUF   32768                    // one quarter: 2 ver * 4 chunk * 4KB
#define RNN_GOFF   (RNN_AOFF + 2 * RNN_ABUF)
#define RNN_SMEM   (RNN_GOFF + 8192)        // + Gpart[2][4][32][8] f32

__global__ void rnn_init(const float* __restrict__ h0l)
{
    int i = blockIdx.x * blockDim.x + threadIdx.x;
    for (int idx = i; idx < B_ * H_; idx += gridDim.x * blockDim.x){
        int b = idx >> 10, k = idx & 1023;
        unsigned short hs, ls;
        split1(h0l[b * H_ + k], hs, ls);
        int off = (k >> 6) * 2048 + b * 64 + (k & 63);
        *(unsigned short*)&g_hsplit[0][off] = hs;
        *(unsigned short*)&g_hsplit[0][off + 32768] = ls;
    }
    if (i == 0) g_bar = 0u;
}

__global__ __launch_bounds__(256, 1) void rnn_kernel(
    const __nv_bfloat16* __restrict__ wsplit,  // this layer, [128 cta][...]
    const float* __restrict__ xproj,
    const float* __restrict__ c0l,
    float* __restrict__ layer_out,
    float* __restrict__ hs_out, float* __restrict__ cs_out)
{
    extern __shared__ char smem[];
    uint32_t sb = smem_u32(smem);
    float* Gpart = (float*)(smem + RNN_GOFF);
    int tid = threadIdx.x;
    int cta = blockIdx.x;
    int lane = tid & 31, wid = tid >> 5;
    int mt = wid & 1, np = (wid >> 1) & 1, kg = wid >> 2;
    int ab = tid >> 3, aj = tid & 7;          // activation role (b, jl)
    int j = cta * 8 + aj;

    // ---- load W slice into smem (swizzled) ----
    {
        const char* wsrc = (const char*)(wsplit + (size_t)cta * 65536);
        for (int r = 0; r < 32; r++){
            int s = tid + r * 256;            // 8192 16B segs
            int seg = s & 7, n = (s >> 3) & 31, ch = (s >> 8) & 15, ver = s >> 12;
            uint32_t d = sw_addr(sb + ver * 65536 + ch * 4096, n, seg);
            cp16(d, wsrc + s * 16);
        }
        asm volatile("cp.async.commit_group;" ::: "memory");
        asm volatile("cp.async.wait_group 0;" ::: "memory");
    }
    float c = c0l[ab * H_ + j];
    __syncthreads();

    unsigned* barp = &g_bar;
    const char* hsb = (const char*)&g_hsplit[0][0];

    // stage quarter q of h(t) into A buffer (q&1)
#define STAGE_Q(t, q)                                                          \
    {                                                                          \
        const char* hb = hsb + ((t) & 1) * 131072;                             \
        uint32_t ab_ = sb + RNN_AOFF + ((q) & 1) * RNN_ABUF;                   \
        for (int r = 0; r < 8; r++){                                           \
            int s = tid + r * 256;       /* 2048 segs */                       \
            int seg = s & 7, b = (s >> 3) & 31, cl = (s >> 8) & 3, vv = s >> 10;\
            int chg = (q) * 4 + cl;                                            \
            const char* src = hb + ((vv * 16 + chg) * 32 + b) * 128 + seg * 16;\
            uint32_t d = sw_addr(ab_ + vv * 16384 + cl * 4096, b, seg);        \
            cp16(d, src);                                                      \
        }                                                                      \
        asm volatile("cp.async.commit_group;" ::: "memory");                   \
    }

    for (int t = 0; t < T_; t++){
        int m = t * B_ + ab;
        const float* xp = xproj + (size_t)m * G4H;
        float x0 = xp[j], x1 = xp[H_ + j], x2 = xp[2 * H_ + j], x3 = xp[3 * H_ + j];

        float acc2[2][4];
#pragma unroll
        for (int i = 0; i < 2; i++)
#pragma unroll
            for (int kidx = 0; kidx < 4; kidx++) acc2[i][kidx] = 0.f;

        STAGE_Q(t, 0);
        asm volatile("cp.async.wait_group 0;" ::: "memory");
        __syncthreads();

        for (int q = 0; q < 4; q++){
            if (q < 3) STAGE_Q(t, q + 1);

            uint32_t abuf = sb + RNN_AOFF + (q & 1) * RNN_ABUF;
#pragma unroll
            for (int cc = 0; cc < 2; cc++){
                int cl = kg * 2 + cc;              // quarter-local chunk
                int chg = q * 4 + cl;              // global chunk
                uint32_t a_hi = abuf + cl * 4096;
                uint32_t a_lo = abuf + 16384 + cl * 4096;
                uint32_t w_hi = sb + chg * 4096;
                uint32_t w_lo = sb + 65536 + chg * 4096;
#pragma unroll
                for (int k16 = 0; k16 < 4; k16++){
                    uint32_t ah[4], al[4], r4[4];
                    uint32_t bh[2][2], bl[2][2];
                    int ar = mt * 16 + (lane & 15);
                    int ac = k16 * 2 + (lane >> 4);
                    ldm_x4(sw_addr(a_hi, ar, ac), ah);
                    ldm_x4(sw_addr(a_lo, ar, ac), al);
                    int br = np * 16 + (lane & 7) + ((lane >> 4) & 1) * 8;
                    int bc = k16 * 2 + ((lane >> 3) & 1);
                    ldm_x4(sw_addr(w_hi, br, bc), r4);
                    bh[0][0] = r4[0]; bh[0][1] = r4[1];
                    bh[1][0] = r4[2]; bh[1][1] = r4[3];
                    ldm_x4(sw_addr(w_lo, br, bc), r4);
                    bl[0][0] = r4[0]; bl[0][1] = r4[1];
                    bl[1][0] = r4[2]; bl[1][1] = r4[3];
                    mma16816(acc2[0], ah, bh[0][0], bh[0][1]);
                    mma16816(acc2[1], ah, bh[1][0], bh[1][1]);
                    mma16816(acc2[0], ah, bl[0][0], bl[0][1]);
                    mma16816(acc2[1], ah, bl[1][0], bl[1][1]);
                    mma16816(acc2[0], al, bh[0][0], bh[0][1]);
                    mma16816(acc2[1], al, bh[1][0], bh[1][1]);
                }
            }
            if (q < 3){
                asm volatile("cp.async.wait_group 0;" ::: "memory");
            }
            __syncthreads();
        }

        // ---- store partials: Gpart[kg][g][m][jl] ----
        {
            int mr = mt * 16 + (lane >> 2);
            int jl0 = (lane & 3) * 2;
#pragma unroll
            for (int n8 = 0; n8 < 2; n8++){
                int g = np * 2 + n8;
                float* p = &Gpart[((kg * 4 + g) * 32 + mr) * 8 + jl0];
                *(float2*)p = make_float2(acc2[n8][0], acc2[n8][1]);
                *(float2*)(p + 64) = make_float2(acc2[n8][2], acc2[n8][3]); // m+8
            }
        }
        __syncthreads();

        // ---- activation: thread (ab, aj) ----
        float s0 = Gpart[((0 + 0) * 32 + ab) * 8 + aj] + Gpart[((4 + 0) * 32 + ab) * 8 + aj];
        float s1 = Gpart[((0 + 1) * 32 + ab) * 8 + aj] + Gpart[((4 + 1) * 32 + ab) * 8 + aj];
        float s2 = Gpart[((0 + 2) * 32 + ab) * 8 + aj] + Gpart[((4 + 2) * 32 + ab) * 8 + aj];
        float s3 = Gpart[((0 + 3) * 32 + ab) * 8 + aj] + Gpart[((4 + 3) * 32 + ab) * 8 + aj];

        float gi = s0 + x0;
        float gf = s1 + x1;
        float gg = s2 + x2;
        float go = s3 + x3;
        float ig = 1.f / (1.f + expf(-gi));
        float fg = 1.f / (1.f + expf(-gf));
        float gt = tanhf(gg);
        float og = 1.f / (1.f + expf(-go));
        c = fg * c + ig * gt;
        float h = og * tanhf(c);

        // publish h as split bf16 into buf (t+1)&1
        {
            unsigned short hs, ls;
            split1(h, hs, ls);
            char* hb = (char*)&g_hsplit[0][0] + ((t + 1) & 1) * 131072;
            int off = ((j >> 6) * 32 + ab) * 128 + (j & 63) * 2;
            *(unsigned short*)(hb + off) = hs;
            *(unsigned short*)(hb + 65536 + off) = ls;
        }
        layer_out[(size_t)m * H_ + j] = h;
        if (t == T_ - 1){ hs_out[ab * H_ + j] = h; cs_out[ab * H_ + j] = c; }

        __threadfence();
        __syncthreads();
        if (t < T_ - 1){
            if (tid == 0){
                atomicAdd(barp, 1u);
                unsigned target = (unsigned)(t + 1) * (unsigned)gridDim.x;
                unsigned v;
                do {
                    asm volatile("ld.acquire.gpu.global.u32 %0, [%1];"
                                 : "=r"(v) : "l"(barp) : "memory");
                } while (v < target);
            }
            __syncthreads();
        }
    }
#undef STAGE_Q
}

// ================================ launch =====================================
extern "C" void kernel_launch(void* const* d_in, const int* in_sizes, int n_in,
                              void* d_out, int out_size)
{
    (void)in_sizes; (void)n_in; (void)out_size;
    const int*   input = (const int*)  d_in[0];
    const float* h0    = (const float*)d_in[1];
    const float* c0    = (const float*)d_in[2];
    const float* embw  = (const float*)d_in[3];
    const float* Wih   = (const float*)d_in[4];
    const float* Whh   = (const float*)d_in[5];
    const float* bih   = (const float*)d_in[6];
    const float* bhh   = (const float*)d_in[7];
    const float* decW  = (const float*)d_in[8];
    const float* decb  = (const float*)d_in[9];
    float* out = (float*)d_out;

    cudaFuncSetAttribute(rnn_kernel, cudaFuncAttributeMaxDynamicSharedMemorySize, RNN_SMEM);
    cudaFuncSetAttribute(mma_gemm,  cudaFuncAttributeMaxDynamicSharedMemorySize, GEMM_SMEM);

    __nv_bfloat16 *p_dec_hi, *p_dec_lo, *p_wih_hi, *p_wih_lo, *p_a_hi, *p_a_lo, *p_wsplit;
    float *p_xproj, *p_out0, *p_out1;
    cudaGetSymbolAddress((void**)&p_dec_hi, g_dec_hi);
    cudaGetSymbolAddress((void**)&p_dec_lo, g_dec_lo);
    cudaGetSymbolAddress((void**)&p_wih_hi, g_wih_hi);
    cudaGetSymbolAddress((void**)&p_wih_lo, g_wih_lo);
    cudaGetSymbolAddress((void**)&p_a_hi,   g_a_hi);
    cudaGetSymbolAddress((void**)&p_a_lo,   g_a_lo);
    cudaGetSymbolAddress((void**)&p_wsplit, g_wsplit);
    cudaGetSymbolAddress((void**)&p_xproj,  g_xproj);
    cudaGetSymbolAddress((void**)&p_out0,   g_out0);
    cudaGetSymbolAddress((void**)&p_out1,   g_out1);

    // weight conversions
    split_kernel<<<8192, 256>>>((const float4*)decW, (ushort4*)p_dec_hi,
                                (ushort4*)p_dec_lo, (int)((size_t)V_ * H_ / 4));
    split_kernel<<<4096, 256>>>((const float4*)Wih, (ushort4*)p_wih_hi,
                                (ushort4*)p_wih_lo, (int)((size_t)L_ * G4H * H_ / 4));
    wsplit_kernel<<<8192, 256>>>(Whh);

    // embedding gather -> bf16 hi/lo
    embed_kernel<<<MROWS, 256>>>(input, embw);

    // layer 0: x_proj = emb @ Wih0^T + bih0 + bhh0
    {
        dim3 grid(MROWS / 128, G4H / 128);
        mma_gemm<<<grid, 256, GEMM_SMEM>>>(p_a_hi, p_a_lo, p_wih_hi, p_wih_lo,
                                           bih, bhh, p_xproj, G4H, H_);
    }
    rnn_init<<<32, 256>>>(h0);
    rnn_kernel<<<REC_CTAS, 256, RNN_SMEM>>>(p_wsplit, p_xproj, c0, p_out0,
                                            out + HS_OFF, out + CS_OFF);

    // layer 1
    split_kernel<<<2048, 256>>>((const float4*)p_out0, (ushort4*)p_a_hi,
                                (ushort4*)p_a_lo, (int)((size_t)MROWS * H_ / 4));
    {
        dim3 grid(MROWS / 128, G4H / 128);
        mma_gemm<<<grid, 256, GEMM_SMEM>>>(p_a_hi, p_a_lo,
                                           p_wih_hi + (size_t)G4H * H_,
                                           p_wih_lo + (size_t)G4H * H_,
                                           bih + G4H, bhh + G4H, p_xproj, G4H, H_);
    }
    rnn_init<<<32, 256>>>(h0 + B_ * H_);
    rnn_kernel<<<REC_CTAS, 256, RNN_SMEM>>>(p_wsplit + (size_t)128 * 65536,
                                            p_xproj, c0 + B_ * H_, p_out1,
                                            out + HS_OFF + B_ * H_,
                                            out + CS_OFF + B_ * H_);

    // decoder
    split_kernel<<<2048, 256>>>((const float4*)p_out1, (ushort4*)p_a_hi,
                                (ushort4*)p_a_lo, (int)((size_t)MROWS * H_ / 4));
    {
        dim3 grid(MROWS / 128, V_ / 128);
        mma_gemm<<<grid, 256, GEMM_SMEM>>>(p_a_hi, p_a_lo, p_dec_hi, p_dec_lo,
                                           decb, nullptr, out, V_, H_);
    }
}

// round 17
// speedup vs baseline: 3.0149x; 1.1125x over previous
#include <cuda_runtime.h>
#include <cuda_bf16.h>
#include <math.h>
#include <stdint.h>

// Problem constants
#define T_ 128
#define B_ 32
#define L_ 2
#define H_ 1024
#define E_ 1024
#define V_ 32000
#define G4H 4096
#define MROWS 4096
#define DEC_OFF ((size_t)T_ * B_ * V_)
#define HS_OFF  (DEC_OFF)
#define CS_OFF  (DEC_OFF + (size_t)L_ * B_ * H_)

// -------------------- scratch (static device memory) ------------------------
__device__ __nv_bfloat16 g_dec_hi[(size_t)V_ * H_];
__device__ __nv_bfloat16 g_dec_lo[(size_t)V_ * H_];
__device__ __nv_bfloat16 g_wih_hi[(size_t)L_ * G4H * H_];
__device__ __nv_bfloat16 g_wih_lo[(size_t)L_ * G4H * H_];
__device__ __nv_bfloat16 g_a_hi[(size_t)MROWS * H_];
__device__ __nv_bfloat16 g_a_lo[(size_t)MROWS * H_];
__device__ float g_xproj[(size_t)MROWS * G4H];
__device__ float g_out0 [(size_t)MROWS * H_];
__device__ float g_out1 [(size_t)MROWS * H_];
// W_hh pre-split per CTA: [L][128 cta][2 ver][16 chunk][32 n][64 k] bf16
__device__ __nv_bfloat16 g_wsplit[(size_t)L_ * 128 * 2 * 16 * 32 * 64];
// h split state: [2 buf][2 ver][16 chunk][32 b][64 k] bf16
__device__ __nv_bfloat16 g_hsplit[2][2 * 16 * 32 * 64];
__device__ unsigned g_bar;

// ============================ helpers ========================================
__device__ __forceinline__ uint32_t smem_u32(const void* p){
    uint32_t a;
    asm("{ .reg .u64 t; cvta.to.shared.u64 t, %1; cvt.u32.u64 %0, t; }"
        : "=r"(a) : "l"(p));
    return a;
}
__device__ __forceinline__ void split1(float x, unsigned short &h, unsigned short &l){
    __nv_bfloat16 bh = __float2bfloat16(x);
    __nv_bfloat16 bl = __float2bfloat16(x - __bfloat162float(bh));
    h = *(unsigned short*)&bh;
    l = *(unsigned short*)&bl;
}
__device__ __forceinline__ uint32_t sw_addr(uint32_t base, int row, int chunk){
    return base + row * 128 + (((chunk ^ (row & 7)) & 7) << 4);
}
__device__ __forceinline__ void ldm_x4(uint32_t addr, uint32_t r[4]){
    asm volatile("ldmatrix.sync.aligned.m8n8.x4.shared.b16 {%0,%1,%2,%3}, [%4];"
                 : "=r"(r[0]), "=r"(r[1]), "=r"(r[2]), "=r"(r[3]) : "r"(addr));
}
__device__ __forceinline__ void mma16816(float c[4], const uint32_t a[4],
                                         const uint32_t b0, const uint32_t b1){
    asm volatile(
        "mma.sync.aligned.m16n8k16.row.col.f32.bf16.bf16.f32 "
        "{%0,%1,%2,%3}, {%4,%5,%6,%7}, {%8,%9}, {%0,%1,%2,%3};"
        : "+f"(c[0]), "+f"(c[1]), "+f"(c[2]), "+f"(c[3])
        : "r"(a[0]), "r"(a[1]), "r"(a[2]), "r"(a[3]), "r"(b0), "r"(b1));
}
__device__ __forceinline__ void cp16(uint32_t d, const void* g){
    asm volatile("cp.async.cg.shared.global [%0], [%1], 16;"
                 :: "r"(d), "l"(g) : "memory");
}

// ======================= fp32 -> bf16 hi/lo conversion =======================
__global__ void split_kernel(const float4* __restrict__ src,
                             ushort4* __restrict__ hi, ushort4* __restrict__ lo,
                             int n4){
    for (int i = blockIdx.x * blockDim.x + threadIdx.x; i < n4;
         i += gridDim.x * blockDim.x){
        float4 v = src[i];
        ushort4 h, l;
        split1(v.x, h.x, l.x); split1(v.y, h.y, l.y);
        split1(v.z, h.z, l.z); split1(v.w, h.w, l.w);
        hi[i] = h; lo[i] = l;
    }
}

// =========== W_hh split + relayout for tensor-core recurrence ================
__global__ void wsplit_kernel(const float* __restrict__ Whh){
    const int total = L_ * G4H * H_;
    for (int i = blockIdx.x * blockDim.x + threadIdx.x; i < total;
         i += gridDim.x * blockDim.x){
        int l = i >> 22;
        int rem = i & 4194303;
        int row = rem >> 10;
        int k = rem & 1023;
        float v = Whh[i];
        unsigned short hs, ls;
        split1(v, hs, ls);
        int g = row >> 10, rr = row & 1023;
        int cta = rr >> 3, jl = rr & 7;
        int n = g * 8 + jl;
        size_t base = ((size_t)(l * 128 + cta)) * 65536;
        size_t idx = base + ((size_t)(k >> 6)) * 2048 + n * 64 + (k & 63);
        *(unsigned short*)&g_wsplit[idx] = hs;
        *(unsigned short*)&g_wsplit[idx + 32768] = ls;
    }
}

// ====================== embedding gather -> bf16 hi/lo =======================
__global__ void embed_kernel(const int* __restrict__ inp,
                             const float* __restrict__ embw){
    int row = blockIdx.x;
    int tok = inp[row];
    const float4* src = (const float4*)(embw + (size_t)tok * E_);
    ushort4* dh = (ushort4*)(g_a_hi + (size_t)row * E_);
    ushort4* dl = (ushort4*)(g_a_lo + (size_t)row * E_);
    float4 v = src[threadIdx.x];
    ushort4 h, l;
    split1(v.x, h.x, l.x); split1(v.y, h.y, l.y);
    split1(v.z, h.z, l.z); split1(v.w, h.w, l.w);
    dh[threadIdx.x] = h; dl[threadIdx.x] = l;
}

// ============ bf16-split NT GEMM via mma.sync (legacy HMMA path) =============
// CTA tile 128(M) x 256(N), 512 threads, warp grid 2x8, warp tile 64x32.
// K-stage = 64 bf16. Stage smem: A_hi 16K | A_lo 16K | B_hi 32K | B_lo 32K.
#define KS 64
#define A_TILE_B (128 * 128)          // 16384
#define B_TILE_B (256 * 128)          // 32768
#define STAGE_B (2 * A_TILE_B + 2 * B_TILE_B)   // 98304
#define GEMM_SMEM (2 * STAGE_B)                 // 196608
#define GEMM_THREADS 512

__global__ __launch_bounds__(GEMM_THREADS, 1)
void mma_gemm(const __nv_bfloat16* __restrict__ Ahi,
              const __nv_bfloat16* __restrict__ Alo,
              const __nv_bfloat16* __restrict__ Bhi,
              const __nv_bfloat16* __restrict__ Blo,
              const float* __restrict__ b1, const float* __restrict__ b2,
              float* __restrict__ C, int N, int K)
{
    extern __shared__ char smem[];
    uint32_t sb = smem_u32(smem);
    int tid = threadIdx.x, wid = tid >> 5, lane = tid & 31;
    int bm = blockIdx.x * 128, bn = blockIdx.y * 256;
    int wm = wid & 1, wn = wid >> 1;        // 2 x 8 warp grid

    float acc[4][4][4];
#pragma unroll
    for (int i = 0; i < 4; i++)
#pragma unroll
        for (int j = 0; j < 4; j++)
#pragma unroll
            for (int k = 0; k < 4; k++) acc[i][j][k] = 0.f;

    const int nst = K / KS;

    // per-stage load: 768 rows (A_hi 128, A_lo 128, B_hi 256, B_lo 256) x 8 segs
#define LOAD_STAGE(s)                                                          \
    {                                                                          \
        uint32_t tb_ = sb + ((s) & 1) * STAGE_B;                               \
        for (int i = tid; i < 6144; i += GEMM_THREADS){                        \
            int seg = i & 7, r = i >> 3;                                       \
            const __nv_bfloat16* src;                                          \
            uint32_t tboff; int grow;                                          \
            if (r < 256){                                                      \
                src = (r < 128) ? Ahi : Alo;                                   \
                tboff = (r < 128) ? 0u : (uint32_t)A_TILE_B;                   \
                grow = bm + (r & 127);                                         \
            } else {                                                           \
                int rb = r - 256;                                              \
                src = (rb < 256) ? Bhi : Blo;                                  \
                tboff = 2 * A_TILE_B + ((rb < 256) ? 0u : (uint32_t)B_TILE_B); \
                grow = bn + (rb & 255);                                        \
            }                                                                  \
            int lrow = (r < 256) ? (r & 127) : ((r - 256) & 255);              \
            const char* g = (const char*)(src + (size_t)grow * K + (s) * KS)   \
                            + seg * 16;                                        \
            uint32_t d = sw_addr(tb_ + tboff, lrow, seg);                      \
            cp16(d, g);                                                        \
        }                                                                      \
        asm volatile("cp.async.commit_group;" ::: "memory");                   \
    }

    LOAD_STAGE(0);

    for (int s = 0; s < nst; s++){
        if (s + 1 < nst) LOAD_STAGE(s + 1);
        if (s + 1 < nst)
            asm volatile("cp.async.wait_group 1;" ::: "memory");
        else
            asm volatile("cp.async.wait_group 0;" ::: "memory");
        __syncthreads();

        uint32_t tb = sb + (s & 1) * STAGE_B;
        uint32_t a_hi_b = tb, a_lo_b = tb + A_TILE_B;
        uint32_t b_hi_b = tb + 2 * A_TILE_B, b_lo_b = b_hi_b + B_TILE_B;

#pragma unroll
        for (int k16 = 0; k16 < KS / 16; k16++){
            uint32_t ah[4][4], al[4][4], bh[4][2], bl[4][2];
            int ar = wm * 64 + (lane & 15);
            int ac = k16 * 2 + (lane >> 4);
#pragma unroll
            for (int mt = 0; mt < 4; mt++){
                ldm_x4(sw_addr(a_hi_b, ar + mt * 16, ac), ah[mt]);
                ldm_x4(sw_addr(a_lo_b, ar + mt * 16, ac), al[mt]);
            }
            int br = wn * 32 + (lane & 7) + ((lane >> 4) & 1) * 8;
            int bc = k16 * 2 + ((lane >> 3) & 1);
#pragma unroll
            for (int np = 0; np < 2; np++){
                uint32_t r4[4];
                ldm_x4(sw_addr(b_hi_b, br + np * 16, bc), r4);
                bh[np * 2][0] = r4[0]; bh[np * 2][1] = r4[1];
                bh[np * 2 + 1][0] = r4[2]; bh[np * 2 + 1][1] = r4[3];
                ldm_x4(sw_addr(b_lo_b, br + np * 16, bc), r4);
                bl[np * 2][0] = r4[0]; bl[np * 2][1] = r4[1];
                bl[np * 2 + 1][0] = r4[2]; bl[np * 2 + 1][1] = r4[3];
            }
            // pass-major order: acc reuse distance = 16 (no RAW stalls)
#pragma unroll
            for (int mt = 0; mt < 4; mt++)
#pragma unroll
                for (int nt = 0; nt < 4; nt++)
                    mma16816(acc[mt][nt], ah[mt], bh[nt][0], bh[nt][1]);
#pragma unroll
            for (int mt = 0; mt < 4; mt++)
#pragma unroll
                for (int nt = 0; nt < 4; nt++)
                    mma16816(acc[mt][nt], ah[mt], bl[nt][0], bl[nt][1]);
#pragma unroll
            for (int mt = 0; mt < 4; mt++)
#pragma unroll
                for (int nt = 0; nt < 4; nt++)
                    mma16816(acc[mt][nt], al[mt], bh[nt][0], bh[nt][1]);
        }
        __syncthreads();
    }

    int m0 = bm + wm * 64 + (lane >> 2);
    int n0 = bn + wn * 32 + (lane & 3) * 2;
#pragma unroll
    for (int nt = 0; nt < 4; nt++){
        int c = n0 + nt * 8;
        float bx = b1[c]     + (b2 ? b2[c]     : 0.f);
        float by = b1[c + 1] + (b2 ? b2[c + 1] : 0.f);
#pragma unroll
        for (int mt = 0; mt < 4; mt++){
            int r = m0 + mt * 16;
            float2 v0 = make_float2(acc[mt][nt][0] + bx, acc[mt][nt][1] + by);
            float2 v1 = make_float2(acc[mt][nt][2] + bx, acc[mt][nt][3] + by);
            *(float2*)&C[(size_t)r * N + c] = v0;
            *(float2*)&C[(size_t)(r + 8) * N + c] = v1;
        }
    }
#undef LOAD_STAGE
}

// ================== LSTM recurrence (persistent, tensor-core) ================
#define REC_CTAS 128
#define RNN_WBYTES (2 * 16 * 32 * 128)      // 131072
#define RNN_AOFF   RNN_WBYTES
#define RNN_ABUF   32768
#define RNN_GOFF   (RNN_AOFF + 2 * RNN_ABUF)
#define RNN_SMEM   (RNN_GOFF + 8192)

__global__ void rnn_init(const float* __restrict__ h0l)
{
    int i = blockIdx.x * blockDim.x + threadIdx.x;
    for (int idx = i; idx < B_ * H_; idx += gridDim.x * blockDim.x){
        int b = idx >> 10, k = idx & 1023;
        unsigned short hs, ls;
        split1(h0l[b * H_ + k], hs, ls);
        int off = (k >> 6) * 2048 + b * 64 + (k & 63);
        *(unsigned short*)&g_hsplit[0][off] = hs;
        *(unsigned short*)&g_hsplit[0][off + 32768] = ls;
    }
    if (i == 0) g_bar = 0u;
}

__global__ __launch_bounds__(256, 1) void rnn_kernel(
    const __nv_bfloat16* __restrict__ wsplit,
    const float* __restrict__ xproj,
    const float* __restrict__ c0l,
    float* __restrict__ layer_out,
    float* __restrict__ hs_out, float* __restrict__ cs_out)
{
    extern __shared__ char smem[];
    uint32_t sb = smem_u32(smem);
    float* Gpart = (float*)(smem + RNN_GOFF);
    int tid = threadIdx.x;
    int cta = blockIdx.x;
    int lane = tid & 31, wid = tid >> 5;
    int mt = wid & 1, np = (wid >> 1) & 1, kg = wid >> 2;
    int ab = tid >> 3, aj = tid & 7;
    int j = cta * 8 + aj;

    {
        const char* wsrc = (const char*)(wsplit + (size_t)cta * 65536);
        for (int r = 0; r < 32; r++){
            int s = tid + r * 256;
            int seg = s & 7, n = (s >> 3) & 31, ch = (s >> 8) & 15, ver = s >> 12;
            uint32_t d = sw_addr(sb + ver * 65536 + ch * 4096, n, seg);
            cp16(d, wsrc + s * 16);
        }
        asm volatile("cp.async.commit_group;" ::: "memory");
        asm volatile("cp.async.wait_group 0;" ::: "memory");
    }
    float c = c0l[ab * H_ + j];
    __syncthreads();

    unsigned* barp = &g_bar;
    const char* hsb = (const char*)&g_hsplit[0][0];

#define STAGE_Q(t, q)                                                          \
    {                                                                          \
        const char* hb = hsb + ((t) & 1) * 131072;                             \
        uint32_t ab_ = sb + RNN_AOFF + ((q) & 1) * RNN_ABUF;                   \
        for (int r = 0; r < 8; r++){                                           \
            int s = tid + r * 256;                                             \
            int seg = s & 7, b = (s >> 3) & 31, cl = (s >> 8) & 3, vv = s >> 10;\
            int chg = (q) * 4 + cl;                                            \
            const char* src = hb + ((vv * 16 + chg) * 32 + b) * 128 + seg * 16;\
            uint32_t d = sw_addr(ab_ + vv * 16384 + cl * 4096, b, seg);        \
            cp16(d, src);                                                      \
        }                                                                      \
        asm volatile("cp.async.commit_group;" ::: "memory");                   \
    }

    for (int t = 0; t < T_; t++){
        int m = t * B_ + ab;
        const float* xp = xproj + (size_t)m * G4H;
        float x0 = xp[j], x1 = xp[H_ + j], x2 = xp[2 * H_ + j], x3 = xp[3 * H_ + j];

        float acc2[2][4];
#pragma unroll
        for (int i = 0; i < 2; i++)
#pragma unroll
            for (int kidx = 0; kidx < 4; kidx++) acc2[i][kidx] = 0.f;

        STAGE_Q(t, 0);
        asm volatile("cp.async.wait_group 0;" ::: "memory");
        __syncthreads();

        for (int q = 0; q < 4; q++){
            if (q < 3) STAGE_Q(t, q + 1);

            uint32_t abuf = sb + RNN_AOFF + (q & 1) * RNN_ABUF;
#pragma unroll
            for (int cc = 0; cc < 2; cc++){
                int cl = kg * 2 + cc;
                int chg = q * 4 + cl;
                uint32_t a_hi = abuf + cl * 4096;
                uint32_t a_lo = abuf + 16384 + cl * 4096;
                uint32_t w_hi = sb + chg * 4096;
                uint32_t w_lo = sb + 65536 + chg * 4096;
#pragma unroll
                for (int k16 = 0; k16 < 4; k16++){
                    uint32_t ah[4], al[4], r4[4];
                    uint32_t bh[2][2], bl[2][2];
                    int ar = mt * 16 + (lane & 15);
                    int ac = k16 * 2 + (lane >> 4);
                    ldm_x4(sw_addr(a_hi, ar, ac), ah);
                    ldm_x4(sw_addr(a_lo, ar, ac), al);
                    int br = np * 16 + (lane & 7) + ((lane >> 4) & 1) * 8;
                    int bc = k16 * 2 + ((lane >> 3) & 1);
                    ldm_x4(sw_addr(w_hi, br, bc), r4);
                    bh[0][0] = r4[0]; bh[0][1] = r4[1];
                    bh[1][0] = r4[2]; bh[1][1] = r4[3];
                    ldm_x4(sw_addr(w_lo, br, bc), r4);
                    bl[0][0] = r4[0]; bl[0][1] = r4[1];
                    bl[1][0] = r4[2]; bl[1][1] = r4[3];
                    mma16816(acc2[0], ah, bh[0][0], bh[0][1]);
                    mma16816(acc2[1], ah, bh[1][0], bh[1][1]);
                    mma16816(acc2[0], ah, bl[0][0], bl[0][1]);
                    mma16816(acc2[1], ah, bl[1][0], bl[1][1]);
                    mma16816(acc2[0], al, bh[0][0], bh[0][1]);
                    mma16816(acc2[1], al, bh[1][0], bh[1][1]);
                }
            }
            if (q < 3){
                asm volatile("cp.async.wait_group 0;" ::: "memory");
            }
            __syncthreads();
        }

        {
            int mr = mt * 16 + (lane >> 2);
            int jl0 = (lane & 3) * 2;
#pragma unroll
            for (int n8 = 0; n8 < 2; n8++){
                int g = np * 2 + n8;
                float* p = &Gpart[((kg * 4 + g) * 32 + mr) * 8 + jl0];
                *(float2*)p = make_float2(acc2[n8][0], acc2[n8][1]);
                *(float2*)(p + 64) = make_float2(acc2[n8][2], acc2[n8][3]);
            }
        }
        __syncthreads();

        float s0 = Gpart[((0 + 0) * 32 + ab) * 8 + aj] + Gpart[((4 + 0) * 32 + ab) * 8 + aj];
        float s1 = Gpart[((0 + 1) * 32 + ab) * 8 + aj] + Gpart[((4 + 1) * 32 + ab) * 8 + aj];
        float s2 = Gpart[((0 + 2) * 32 + ab) * 8 + aj] + Gpart[((4 + 2) * 32 + ab) * 8 + aj];
        float s3 = Gpart[((0 + 3) * 32 + ab) * 8 + aj] + Gpart[((4 + 3) * 32 + ab) * 8 + aj];

        float gi = s0 + x0;
        float gf = s1 + x1;
        float gg = s2 + x2;
        float go = s3 + x3;
        float ig = 1.f / (1.f + expf(-gi));
        float fg = 1.f / (1.f + expf(-gf));
        float gt = tanhf(gg);
        float og = 1.f / (1.f + expf(-go));
        c = fg * c + ig * gt;
        float h = og * tanhf(c);

        {
            unsigned short hs, ls;
            split1(h, hs, ls);
            char* hb = (char*)&g_hsplit[0][0] + ((t + 1) & 1) * 131072;
            int off = ((j >> 6) * 32 + ab) * 128 + (j & 63) * 2;
            *(unsigned short*)(hb + off) = hs;
            *(unsigned short*)(hb + 65536 + off) = ls;
        }
        layer_out[(size_t)m * H_ + j] = h;
        if (t == T_ - 1){ hs_out[ab * H_ + j] = h; cs_out[ab * H_ + j] = c; }

        __threadfence();
        __syncthreads();
        if (t < T_ - 1){
            if (tid == 0){
                atomicAdd(barp, 1u);
                unsigned target = (unsigned)(t + 1) * (unsigned)gridDim.x;
                unsigned v;
                do {
                    asm volatile("ld.acquire.gpu.global.u32 %0, [%1];"
                                 : "=r"(v) : "l"(barp) : "memory");
                } while (v < target);
            }
            __syncthreads();
        }
    }
#undef STAGE_Q
}

// ================================ launch =====================================
extern "C" void kernel_launch(void* const* d_in, const int* in_sizes, int n_in,
                              void* d_out, int out_size)
{
    (void)in_sizes; (void)n_in; (void)out_size;
    const int*   input = (const int*)  d_in[0];
    const float* h0    = (const float*)d_in[1];
    const float* c0    = (const float*)d_in[2];
    const float* embw  = (const float*)d_in[3];
    const float* Wih   = (const float*)d_in[4];
    const float* Whh   = (const float*)d_in[5];
    const float* bih   = (const float*)d_in[6];
    const float* bhh   = (const float*)d_in[7];
    const float* decW  = (const float*)d_in[8];
    const float* decb  = (const float*)d_in[9];
    float* out = (float*)d_out;

    cudaFuncSetAttribute(rnn_kernel, cudaFuncAttributeMaxDynamicSharedMemorySize, RNN_SMEM);
    cudaFuncSetAttribute(mma_gemm,  cudaFuncAttributeMaxDynamicSharedMemorySize, GEMM_SMEM);

    __nv_bfloat16 *p_dec_hi, *p_dec_lo, *p_wih_hi, *p_wih_lo, *p_a_hi, *p_a_lo, *p_wsplit;
    float *p_xproj, *p_out0, *p_out1;
    cudaGetSymbolAddress((void**)&p_dec_hi, g_dec_hi);
    cudaGetSymbolAddress((void**)&p_dec_lo, g_dec_lo);
    cudaGetSymbolAddress((void**)&p_wih_hi, g_wih_hi);
    cudaGetSymbolAddress((void**)&p_wih_lo, g_wih_lo);
    cudaGetSymbolAddress((void**)&p_a_hi,   g_a_hi);
    cudaGetSymbolAddress((void**)&p_a_lo,   g_a_lo);
    cudaGetSymbolAddress((void**)&p_wsplit, g_wsplit);
    cudaGetSymbolAddress((void**)&p_xproj,  g_xproj);
    cudaGetSymbolAddress((void**)&p_out0,   g_out0);
    cudaGetSymbolAddress((void**)&p_out1,   g_out1);

    // weight conversions
    split_kernel<<<8192, 256>>>((const float4*)decW, (ushort4*)p_dec_hi,
                                (ushort4*)p_dec_lo, (int)((size_t)V_ * H_ / 4));
    split_kernel<<<4096, 256>>>((const float4*)Wih, (ushort4*)p_wih_hi,
                                (ushort4*)p_wih_lo, (int)((size_t)L_ * G4H * H_ / 4));
    wsplit_kernel<<<8192, 256>>>(Whh);

    // embedding gather -> bf16 hi/lo
    embed_kernel<<<MROWS, 256>>>(input, embw);

    // layer 0: x_proj = emb @ Wih0^T + bih0 + bhh0
    {
        dim3 grid(MROWS / 128, G4H / 256);
        mma_gemm<<<grid, GEMM_THREADS, GEMM_SMEM>>>(p_a_hi, p_a_lo, p_wih_hi, p_wih_lo,
                                                    bih, bhh, p_xproj, G4H, H_);
    }
    rnn_init<<<32, 256>>>(h0);
    rnn_kernel<<<REC_CTAS, 256, RNN_SMEM>>>(p_wsplit, p_xproj, c0, p_out0,
                                            out + HS_OFF, out + CS_OFF);

    // layer 1
    split_kernel<<<2048, 256>>>((const float4*)p_out0, (ushort4*)p_a_hi,
                                (ushort4*)p_a_lo, (int)((size_t)MROWS * H_ / 4));
    {
        dim3 grid(MROWS / 128, G4H / 256);
        mma_gemm<<<grid, GEMM_THREADS, GEMM_SMEM>>>(p_a_hi, p_a_lo,
                                                    p_wih_hi + (size_t)G4H * H_,
                                                    p_wih_lo + (size_t)G4H * H_,
                                                    bih + G4H, bhh + G4H, p_xproj, G4H, H_);
    }
    rnn_init<<<32, 256>>>(h0 + B_ * H_);
    rnn_kernel<<<REC_CTAS, 256, RNN_SMEM>>>(p_wsplit + (size_t)128 * 65536,
                                            p_xproj, c0 + B_ * H_, p_out1,
                                            out + HS_OFF + B_ * H_,
                                            out + CS_OFF + B_ * H_);

    // decoder: N = 32000 = 125 * 256
    split_kernel<<<2048, 256>>>((const float4*)p_out1, (ushort4*)p_a_hi,
                                (ushort4*)p_a_lo, (int)((size_t)MROWS * H_ / 4));
    {
        dim3 grid(MROWS / 128, V_ / 256);
        mma_gemm<<<grid, GEMM_THREADS, GEMM_SMEM>>>(p_a_hi, p_a_lo, p_dec_hi, p_dec_lo,
                                                    decb, nullptr, out, V_, H_);
    }
}